// round 2
// baseline (speedup 1.0000x reference)
#include <cuda_runtime.h>
#include <math.h>

#define BQ   2
#define LQ   96
#define HQ   2
#define EE   63
#define NC1  64
#define NC2  128
#define KSZ  3
#define CCH  192
#define LTT  94
#define NTT  93
#define NNN  187
#define OO   256
#define SIGD 37056
#define NH   4
#define EVD  64

__device__ float d_AT[2][NH][CCH][LTT];   // augmented features [w][head][c][t]
__device__ float d_P[2][NH][NTT][OO];     // projected signatures

// ---------------------------------------------------------------------------
// Kernel 1: augmentation (trunc | time | relu(conv2(conv1(x))))
// ---------------------------------------------------------------------------
__global__ __launch_bounds__(256) void k_augment(
    const float* __restrict__ qg, const float* __restrict__ kg,
    const float* __restrict__ Wq1, const float* __restrict__ bq1,
    const float* __restrict__ Wq2, const float* __restrict__ bq2,
    const float* __restrict__ Wk1, const float* __restrict__ bk1,
    const float* __restrict__ Wk2, const float* __restrict__ bk2)
{
    __shared__ float xs[LQ][EE + 2];
    __shared__ float y1s[NC1][48];

    int wh = blockIdx.x;
    int w = wh >> 2, head = wh & 3;
    int b = head >> 1, h = head & 1;
    int t0 = blockIdx.y * 47;
    const float* x  = w ? kg  : qg;
    const float* W1 = w ? Wk1 : Wq1;
    const float* B1 = w ? bk1 : bq1;
    const float* W2 = w ? Wk2 : Wq2;
    const float* B2 = w ? bk2 : bq2;
    int tid = threadIdx.x;

    for (int idx = tid; idx < LQ * EE; idx += 256) {
        int l = idx / EE, e = idx - l * EE;
        xs[l][e] = x[((b * LQ + l) * HQ + h) * EE + e];
    }
    __syncthreads();

    for (int idx = tid; idx < NC1 * 47; idx += 256) {
        int tl = idx % 47, c = idx / 47;
        int t = t0 + tl;
        float acc = B1[c];
        const float* wr = W1 + c * (EE * KSZ);
        #pragma unroll 7
        for (int e = 0; e < EE; e++) {
            acc += wr[e * 3 + 0] * xs[t][e]
                 + wr[e * 3 + 1] * xs[t + 1][e]
                 + wr[e * 3 + 2] * xs[t + 2][e];
        }
        y1s[c][tl] = acc;
    }
    __syncthreads();

    for (int idx = tid; idx < NC2 * 47; idx += 256) {
        int tl = idx % 47, c = idx / 47;
        int t = t0 + tl;
        float acc = B2[c];
        const float* wr = W2 + c * NC1;
        #pragma unroll
        for (int j = 0; j < NC1; j++) acc += wr[j] * y1s[j][tl];
        d_AT[w][head][64 + c][t] = fmaxf(acc, 0.0f);
    }
    for (int idx = tid; idx < 64 * 47; idx += 256) {
        int tl = idx % 47, c = idx / 47;
        int t = t0 + tl;
        d_AT[w][head][c][t] = (c == 63) ? (t * (1.0f / 93.0f)) : xs[t + 2][c];
    }
}

// ---------------------------------------------------------------------------
// Kernel 2: per-o fused  Z = W2[o]@A  + tridiagonal dots + scan + P assembly
// grid (256, 2, 2), 256 threads, 226.5 KB dynamic smem, 1 CTA/SM
// ---------------------------------------------------------------------------
#define WS 194

__global__ __launch_bounds__(256, 1) void k_proj(
    const float* __restrict__ Wlq, const float* __restrict__ blq,
    const float* __restrict__ Wlk, const float* __restrict__ blk)
{
    extern __shared__ float sm[];
    float* Wsh    = sm;                 // [192][WS]
    float* Ash    = Wsh + CCH * WS;     // [96][WS]  (rows 94,95 zero)
    float* w1sh   = Ash + 96 * WS;      // [192]
    float* alphaS = w1sh + CCH;         // [94]
    float* deltaS = alphaS + LTT;       // [94]
    float* eS     = deltaS + LTT;       // [94]
    float* betaS  = eS + LTT;           // [93]
    float* gammaS = betaS + NTT;        // [93]
    float* prefS  = gammaS + NTT;       // [93]

    int o = blockIdx.x;
    int w = blockIdx.y;
    int hp = blockIdx.z;
    const float* Wl = w ? Wlk : Wlq;
    const float* bl = w ? blk : blq;
    int tid = threadIdx.x, lane = tid & 31, warp = tid >> 5;

    const float* Wsrc = Wl + (size_t)o * SIGD + CCH;
    for (int g = tid; g < CCH * CCH; g += 256) {
        int i = g / CCH, j = g - i * CCH;
        Wsh[i * WS + j] = Wsrc[g];
    }
    for (int g = tid; g < CCH; g += 256) w1sh[g] = Wl[(size_t)o * SIGD + g];
    float blo = bl[o];

    for (int hh = 0; hh < 2; hh++) {
        int head = hp * 2 + hh;
        __syncthreads();

        const float* Asrc = &d_AT[w][head][0][0];
        for (int g = tid; g < CCH * LTT; g += 256) {
            int c = g / LTT, t = g - c * LTT;
            Ash[t * WS + c] = Asrc[g];
        }
        for (int g = tid; g < 2 * CCH; g += 256) {
            int t = 94 + g / CCH, c = g % CCH;
            Ash[t * WS + c] = 0.0f;
        }
        __syncthreads();

        // Z[i][t], i = lane+32m, t = warp*12+r
        float acc[6][12];
        #pragma unroll
        for (int m = 0; m < 6; m++)
            #pragma unroll
            for (int r = 0; r < 12; r++) acc[m][r] = 0.0f;

        int tbase = warp * 12;
        #pragma unroll 2
        for (int j = 0; j < CCH; j += 2) {
            float2 wv[6], av[12];
            #pragma unroll
            for (int m = 0; m < 6; m++)
                wv[m] = *(const float2*)&Wsh[(lane + 32 * m) * WS + j];
            #pragma unroll
            for (int r = 0; r < 12; r++)
                av[r] = *(const float2*)&Ash[(tbase + r) * WS + j];
            #pragma unroll
            for (int r = 0; r < 12; r++)
                #pragma unroll
                for (int m = 0; m < 6; m++) {
                    acc[m][r] += wv[m].x * av[r].x;
                    acc[m][r] += wv[m].y * av[r].y;
                }
        }

        #pragma unroll
        for (int r = 0; r < 12; r++) {
            int t = tbase + r;
            if (t >= LTT) continue;
            float pa = 0, pd = 0, pb = 0, pg = 0, pe = 0;
            int tm1 = (t >= 1) ? t - 1 : 0;
            #pragma unroll
            for (int m = 0; m < 6; m++) {
                int i = lane + 32 * m;
                float z = acc[m][r];
                pa += z * Ash[t * WS + i];
                pd += z * Ash[i];
                pb += z * Ash[tm1 * WS + i];
                pg += z * Ash[(t + 1) * WS + i];
                pe += w1sh[i] * Ash[t * WS + i];
            }
            #pragma unroll
            for (int off = 16; off; off >>= 1) {
                pa += __shfl_down_sync(0xffffffffu, pa, off);
                pd += __shfl_down_sync(0xffffffffu, pd, off);
                pb += __shfl_down_sync(0xffffffffu, pb, off);
                pg += __shfl_down_sync(0xffffffffu, pg, off);
                pe += __shfl_down_sync(0xffffffffu, pe, off);
            }
            if (lane == 0) {
                alphaS[t] = pa;
                deltaS[t] = pd;
                eS[t] = pe;
                if (t >= 1)  betaS[t - 1] = pb;
                if (t <= 92) gammaS[t] = pg;
            }
        }
        __syncthreads();

        if (warp == 0) {
            float carry = 0.0f;
            for (int ch = 0; ch < 3; ch++) {
                int idx = ch * 32 + lane;
                float vv = (idx < NTT) ? (betaS[idx] - gammaS[idx]) : 0.0f;
                #pragma unroll
                for (int off = 1; off < 32; off <<= 1) {
                    float n = __shfl_up_sync(0xffffffffu, vv, off);
                    if (lane >= off) vv += n;
                }
                vv += carry;
                if (idx < NTT) prefS[idx] = vv;
                carry = __shfl_sync(0xffffffffu, vv, 31);
            }
        }
        __syncthreads();

        if (tid < NTT) {
            int t = tid;
            float Pv = blo + eS[t + 1] - eS[0]
                     + 0.5f * (alphaS[t + 1] + alphaS[0])
                     - deltaS[t + 1]
                     + 0.5f * prefS[t];
            d_P[w][head][t][o] = Pv;
        }
    }
}

// ---------------------------------------------------------------------------
// Kernel 3: attn = tanh(Pq @ Pk^T) on 93x93 core; out = attn @ v_agg
// ---------------------------------------------------------------------------
#define TS 260

__global__ __launch_bounds__(256) void k_attn(
    const float* __restrict__ v, float* __restrict__ out)
{
    extern __shared__ float sm3[];
    float* Tq = sm3;                 // [93][TS]
    float* Tk = Tq + NTT * TS;       // [93][TS]
    float* vg = Tk + NTT * TS;       // [93][64]
    float* Gr = vg + NTT * EVD;      // [8][96]

    int bh = blockIdx.x, zh = blockIdx.y;
    int tid = threadIdx.x, lane = tid & 31, warp = tid >> 5;

    for (int g = tid; g < NTT * OO; g += 256) {
        int t = g >> 8, o = g & 255;
        Tq[t * TS + o] = d_P[0][bh][t][o];
        Tk[t * TS + o] = d_P[1][bh][t][o];
    }
    for (int g = tid; g < NTT * EVD; g += 256) {
        int t = g >> 6, e = g & 63;
        float s = v[((size_t)bh * NNN + 2 * t) * EVD + e]
                + v[((size_t)bh * NNN + 2 * t + 1) * EVD + e];
        if (t == 92) s += v[((size_t)bh * NNN + 186) * EVD + e];
        vg[g] = s;
    }
    __syncthreads();

    int x0 = zh * 48;
    for (int xx = 0; xx < 6; xx++) {
        int x = x0 + warp + 8 * xx;
        if (x < NTT) {
            int ty0 = lane, ty1 = lane + 32, ty2 = lane + 64;
            int ty2c = (ty2 < NTT) ? ty2 : 0;
            const float4* tq = (const float4*)(Tq + x * TS);
            const float4* k0 = (const float4*)(Tk + ty0 * TS);
            const float4* k1 = (const float4*)(Tk + ty1 * TS);
            const float4* k2 = (const float4*)(Tk + ty2c * TS);
            float a0 = 0, a1 = 0, a2 = 0;
            #pragma unroll 8
            for (int o4 = 0; o4 < OO / 4; o4++) {
                float4 qv = tq[o4];
                float4 b0 = k0[o4];
                a0 += qv.x * b0.x + qv.y * b0.y + qv.z * b0.z + qv.w * b0.w;
                float4 b1 = k1[o4];
                a1 += qv.x * b1.x + qv.y * b1.y + qv.z * b1.z + qv.w * b1.w;
                float4 b2 = k2[o4];
                a2 += qv.x * b2.x + qv.y * b2.y + qv.z * b2.z + qv.w * b2.w;
            }
            __syncwarp();
            Gr[warp * 96 + ty0] = tanhf(a0);
            Gr[warp * 96 + ty1] = tanhf(a1);
            if (ty2 < NTT) Gr[warp * 96 + ty2] = tanhf(a2);
            __syncwarp();
            float o0 = 0, o1 = 0;
            for (int ty = 0; ty < NTT; ty++) {
                float g = Gr[warp * 96 + ty];
                o0 += g * vg[ty * EVD + lane];
                o1 += g * vg[ty * EVD + lane + 32];
            }
            size_t base = ((size_t)bh * NNN + 2 * x) * EVD;
            out[base + lane]            = o0;
            out[base + lane + 32]       = o1;
            out[base + EVD + lane]      = o0;
            out[base + EVD + lane + 32] = o1;
            if (x == 92) {
                size_t bl2 = ((size_t)bh * NNN + 186) * EVD;
                out[bl2 + lane]      = o0;
                out[bl2 + lane + 32] = o1;
            }
        }
    }
}

// ---------------------------------------------------------------------------
extern "C" void kernel_launch(void* const* d_in, const int* in_sizes, int n_in,
                              void* d_out, int out_size)
{
    const float* q   = (const float*)d_in[0];
    const float* k   = (const float*)d_in[1];
    const float* v   = (const float*)d_in[2];
    const float* Wq1 = (const float*)d_in[3];
    const float* bq1 = (const float*)d_in[4];
    const float* Wq2 = (const float*)d_in[5];
    const float* bq2 = (const float*)d_in[6];
    const float* Wk1 = (const float*)d_in[7];
    const float* bk1 = (const float*)d_in[8];
    const float* Wk2 = (const float*)d_in[9];
    const float* bk2 = (const float*)d_in[10];
    const float* Wlq = (const float*)d_in[11];
    const float* blq = (const float*)d_in[12];
    const float* Wlk = (const float*)d_in[13];
    const float* blk = (const float*)d_in[14];
    float* out = (float*)d_out;

    const int SM2 = (CCH * WS + 96 * WS + CCH + 3 * LTT + 3 * NTT) * 4;
    const int SM3 = (2 * NTT * TS + NTT * EVD + 8 * 96) * 4;
    static int attr_done = 0;
    if (!attr_done) {
        cudaFuncSetAttribute(k_proj, cudaFuncAttributeMaxDynamicSharedMemorySize, SM2);
        cudaFuncSetAttribute(k_attn, cudaFuncAttributeMaxDynamicSharedMemorySize, SM3);
        attr_done = 1;
    }

    k_augment<<<dim3(8, 2), 256>>>(q, k, Wq1, bq1, Wq2, bq2, Wk1, bk1, Wk2, bk2);
    k_proj<<<dim3(256, 2, 2), 256, SM2>>>(Wlq, blq, Wlk, blk);
    k_attn<<<dim3(4, 2), 256, SM3>>>(v, out);
}

// round 4
// speedup vs baseline: 1.0519x; 1.0519x over previous
#include <cuda_runtime.h>
#include <cuda_bf16.h>
#include <mma.h>
#include <cstdint>
#include <math.h>

using namespace nvcuda;

#define CCH  192
#define LTT  94
#define NTT  93
#define NNN  187
#define OO   256
#define SIGD 37056
#define EVD  64

__device__ float d_ATt[2][4][LTT][CCH];   // augmented features, t-major
__device__ float d_P[2][4][NTT][OO];      // projected signatures

// ---------------------------------------------------------------------------
// Kernel 1: augmentation -> d_ATt[w][head][t][c]   grid (8, 8), 256 thr
// ---------------------------------------------------------------------------
__global__ __launch_bounds__(256) void k_augment(
    const float* __restrict__ qg, const float* __restrict__ kg,
    const float* __restrict__ Wq1, const float* __restrict__ bq1,
    const float* __restrict__ Wq2, const float* __restrict__ bq2,
    const float* __restrict__ Wk1, const float* __restrict__ bk1,
    const float* __restrict__ Wk2, const float* __restrict__ bk2)
{
    __shared__ float xs[14][64];
    __shared__ float y1s[64][12];

    int wh = blockIdx.x;
    int w = wh >> 2, head = wh & 3;
    int b = head >> 1, h = head & 1;
    int t0 = blockIdx.y * 12;
    const float* x  = w ? kg  : qg;
    const float* W1 = w ? Wk1 : Wq1;
    const float* B1 = w ? bk1 : bq1;
    const float* W2 = w ? Wk2 : Wq2;
    const float* B2 = w ? bk2 : bq2;
    int tid = threadIdx.x;

    for (int idx = tid; idx < 14 * 63; idx += 256) {
        int r = idx / 63, e = idx - r * 63;
        int l = t0 + r;
        if (l < 96) xs[r][e] = x[((b * 96 + l) * 2 + h) * 63 + e];
    }
    __syncthreads();

    for (int idx = tid; idx < 64 * 12; idx += 256) {
        int c = idx / 12, tl = idx - c * 12;
        int t = t0 + tl;
        float acc = 0.0f;
        if (t < LTT) {
            acc = B1[c];
            const float* wr = W1 + c * 189;
            #pragma unroll 7
            for (int e = 0; e < 63; e++) {
                acc += wr[e * 3 + 0] * xs[tl][e]
                     + wr[e * 3 + 1] * xs[tl + 1][e]
                     + wr[e * 3 + 2] * xs[tl + 2][e];
            }
        }
        y1s[c][tl] = acc;
    }
    __syncthreads();

    for (int idx = tid; idx < 128 * 12; idx += 256) {
        int c = idx / 12, tl = idx - c * 12;
        int t = t0 + tl;
        if (t < LTT) {
            float acc = B2[c];
            const float* wr = W2 + c * 64;
            #pragma unroll
            for (int j = 0; j < 64; j++) acc += wr[j] * y1s[j][tl];
            d_ATt[w][head][t][64 + c] = fmaxf(acc, 0.0f);
        }
    }
    for (int idx = tid; idx < 64 * 12; idx += 256) {
        int tl = idx >> 6, c = idx & 63;
        int t = t0 + tl;
        if (t < LTT)
            d_ATt[w][head][t][c] = (c == 63) ? (t * (1.0f / 93.0f)) : xs[tl + 2][c];
    }
}

// ---------------------------------------------------------------------------
// Kernel 2: wmma bf16-split  Z = A @ W2half^T  + dots + scan + P
// grid (256, 2), 256 threads, ~201 KB dynamic smem, 1 CTA/SM
// ---------------------------------------------------------------------------
#define WS2 200   // bf16 row stride (16B-aligned, != mult of 64 -> no LDSM conflicts)
#define DS  100   // fp32 row stride for D (mult of 4 for wmma store)

// byte offsets in dynamic smem
#define OFF_WHI  0
#define OFF_WLO  38400
#define OFF_AHI  76800
#define OFF_ALO  115200
#define OFF_D    153600
#define OFF_W1   192000
#define OFF_ACC  192768    // [4 heads][5][96] fp32 (0=alpha 1=delta 2=beta 3=gamma 4=e)
#define OFF_PREF 200448
#define SM_TOT   200832

__device__ __forceinline__ void split_bf16(float v, __nv_bfloat16& hi, __nv_bfloat16& lo) {
    hi = __float2bfloat16(v);
    lo = __float2bfloat16(v - __bfloat162float(hi));
}

__global__ __launch_bounds__(256, 1) void k_proj(
    const float* __restrict__ Wlq, const float* __restrict__ blq,
    const float* __restrict__ Wlk, const float* __restrict__ blk)
{
    extern __shared__ char sm[];
    __nv_bfloat16* Whi = (__nv_bfloat16*)(sm + OFF_WHI);
    __nv_bfloat16* Wlo = (__nv_bfloat16*)(sm + OFF_WLO);
    __nv_bfloat16* Ahi = (__nv_bfloat16*)(sm + OFF_AHI);
    __nv_bfloat16* Alo = (__nv_bfloat16*)(sm + OFF_ALO);
    float* Dsh   = (float*)(sm + OFF_D);
    float* w1sh  = (float*)(sm + OFF_W1);
    float* accS  = (float*)(sm + OFF_ACC);
    float* prefS = (float*)(sm + OFF_PREF);

    int o = blockIdx.x, w = blockIdx.y;
    const float* Wl = w ? Wlk : Wlq;
    const float* bl = w ? blk : blq;
    int tid = threadIdx.x, lane = tid & 31, warp = tid >> 5;

    for (int g = tid; g < CCH; g += 256) w1sh[g] = Wl[(size_t)o * SIGD + g];
    float blo = bl[o];

    for (int half = 0; half < 2; half++) {
        // ---- W2 half -> bf16 hi/lo ----
        __syncthreads();
        const float* Wsrc = Wl + (size_t)o * SIGD + CCH + (size_t)half * 96 * CCH;
        for (int g = tid; g < 96 * CCH; g += 256) {
            int i = g / CCH, j = g - i * CCH;
            __nv_bfloat16 hi, lo;
            split_bf16(Wsrc[g], hi, lo);
            Whi[i * WS2 + j] = hi;
            Wlo[i * WS2 + j] = lo;
        }
        __syncthreads();

        for (int head = 0; head < 4; head++) {
            // ---- A -> bf16 hi/lo (rows 94,95 zeroed) ----
            const float* Asrc = &d_ATt[w][head][0][0];
            for (int g = tid; g < 96 * CCH; g += 256) {
                int t = g / CCH, j = g - t * CCH;
                float v = (t < LTT) ? Asrc[g] : 0.0f;
                __nv_bfloat16 hi, lo;
                split_bf16(v, hi, lo);
                Ahi[t * WS2 + j] = hi;
                Alo[t * WS2 + j] = lo;
            }
            __syncthreads();

            // ---- MMA: D[96][96] = A[96x192] @ Whalf^T, 3 split passes ----
            for (int tt = warp; tt < 36; tt += 8) {
                int mt = tt / 6, nt = tt % 6;
                wmma::fragment<wmma::accumulator, 16, 16, 16, float> fc;
                wmma::fill_fragment(fc, 0.0f);
                #pragma unroll
                for (int k = 0; k < 12; k++) {
                    wmma::fragment<wmma::matrix_a, 16, 16, 16, __nv_bfloat16, wmma::row_major> fa_hi, fa_lo;
                    wmma::fragment<wmma::matrix_b, 16, 16, 16, __nv_bfloat16, wmma::col_major> fb_hi, fb_lo;
                    wmma::load_matrix_sync(fa_hi, Ahi + mt * 16 * WS2 + k * 16, WS2);
                    wmma::load_matrix_sync(fa_lo, Alo + mt * 16 * WS2 + k * 16, WS2);
                    wmma::load_matrix_sync(fb_hi, Whi + nt * 16 * WS2 + k * 16, WS2);
                    wmma::load_matrix_sync(fb_lo, Wlo + nt * 16 * WS2 + k * 16, WS2);
                    wmma::mma_sync(fc, fa_hi, fb_hi, fc);
                    wmma::mma_sync(fc, fa_hi, fb_lo, fc);
                    wmma::mma_sync(fc, fa_lo, fb_hi, fc);
                }
                wmma::store_matrix_sync(Dsh + mt * 16 * DS + nt * 16, fc, DS, wmma::mem_row_major);
            }
            __syncthreads();

            // ---- tridiagonal dots (+ e on half 0); warp w owns t = 12w..12w+11
            for (int r = 0; r < 12; r++) {
                int t = warp * 12 + r;
                if (t >= LTT) continue;
                int tm1 = (t >= 1) ? t - 1 : 0;
                float pa = 0, pd = 0, pb = 0, pg = 0, pe = 0;
                #pragma unroll
                for (int m = 0; m < 3; m++) {
                    int il = lane + 32 * m;
                    int c = half * 96 + il;
                    float z = Dsh[t * DS + il];
                    float at  = __bfloat162float(Ahi[t * WS2 + c])       + __bfloat162float(Alo[t * WS2 + c]);
                    float a0  = __bfloat162float(Ahi[c])                 + __bfloat162float(Alo[c]);
                    float atm = __bfloat162float(Ahi[tm1 * WS2 + c])     + __bfloat162float(Alo[tm1 * WS2 + c]);
                    float atp = __bfloat162float(Ahi[(t + 1) * WS2 + c]) + __bfloat162float(Alo[(t + 1) * WS2 + c]);
                    pa += z * at; pd += z * a0; pb += z * atm; pg += z * atp;
                }
                if (half == 0) {
                    #pragma unroll
                    for (int m = 0; m < 6; m++) {
                        int j = lane + 32 * m;
                        pe += w1sh[j] * (__bfloat162float(Ahi[t * WS2 + j]) + __bfloat162float(Alo[t * WS2 + j]));
                    }
                }
                #pragma unroll
                for (int off = 16; off; off >>= 1) {
                    pa += __shfl_down_sync(0xffffffffu, pa, off);
                    pd += __shfl_down_sync(0xffffffffu, pd, off);
                    pb += __shfl_down_sync(0xffffffffu, pb, off);
                    pg += __shfl_down_sync(0xffffffffu, pg, off);
                    pe += __shfl_down_sync(0xffffffffu, pe, off);
                }
                if (lane == 0) {
                    float* acc = accS + head * 480;
                    if (half == 0) {
                        acc[0 * 96 + t] = pa;
                        acc[1 * 96 + t] = pd;
                        if (t >= 1)  acc[2 * 96 + t - 1] = pb;
                        if (t <= 92) acc[3 * 96 + t] = pg;
                        acc[4 * 96 + t] = pe;
                    } else {
                        acc[0 * 96 + t] += pa;
                        acc[1 * 96 + t] += pd;
                        if (t >= 1)  acc[2 * 96 + t - 1] += pb;
                        if (t <= 92) acc[3 * 96 + t] += pg;
                    }
                }
            }
            __syncthreads();
        }
    }

    // ---- per-head scan + P assembly ----
    for (int head = 0; head < 4; head++) {
        float* acc = accS + head * 480;
        if (warp == 0) {
            float carry = 0.0f;
            for (int ch = 0; ch < 3; ch++) {
                int idx = ch * 32 + lane;
                float vv = (idx < NTT) ? (acc[2 * 96 + idx] - acc[3 * 96 + idx]) : 0.0f;
                #pragma unroll
                for (int off = 1; off < 32; off <<= 1) {
                    float n = __shfl_up_sync(0xffffffffu, vv, off);
                    if (lane >= off) vv += n;
                }
                vv += carry;
                if (idx < NTT) prefS[idx] = vv;
                carry = __shfl_sync(0xffffffffu, vv, 31);
            }
        }
        __syncthreads();
        if (tid < NTT) {
            int t = tid;
            float Pv = blo + acc[4 * 96 + t + 1] - acc[4 * 96 + 0]
                     + 0.5f * (acc[0 * 96 + t + 1] + acc[0 * 96 + 0])
                     - acc[1 * 96 + t + 1]
                     + 0.5f * prefS[t];
            d_P[w][head][t][o] = Pv;
        }
        __syncthreads();
    }
}

// ---------------------------------------------------------------------------
// Kernel 3: attn = tanh(Pq @ Pk^T) on 93x93 core; out = attn @ v_agg
// ---------------------------------------------------------------------------
#define TS 260

__global__ __launch_bounds__(256) void k_attn(
    const float* __restrict__ v, float* __restrict__ out)
{
    extern __shared__ float sm3[];
    float* Tq = sm3;
    float* Tk = Tq + NTT * TS;
    float* vg = Tk + NTT * TS;
    float* Gr = vg + NTT * EVD;

    int bh = blockIdx.x, zh = blockIdx.y;
    int tid = threadIdx.x, lane = tid & 31, warp = tid >> 5;

    for (int g = tid; g < NTT * OO; g += 256) {
        int t = g >> 8, o = g & 255;
        Tq[t * TS + o] = d_P[0][bh][t][o];
        Tk[t * TS + o] = d_P[1][bh][t][o];
    }
    for (int g = tid; g < NTT * EVD; g += 256) {
        int t = g >> 6, e = g & 63;
        float s = v[((size_t)bh * NNN + 2 * t) * EVD + e]
                + v[((size_t)bh * NNN + 2 * t + 1) * EVD + e];
        if (t == 92) s += v[((size_t)bh * NNN + 186) * EVD + e];
        vg[g] = s;
    }
    __syncthreads();

    int x0 = zh * 48;
    for (int xx = 0; xx < 6; xx++) {
        int x = x0 + warp + 8 * xx;
        if (x < NTT) {
            int ty0 = lane, ty1 = lane + 32, ty2 = lane + 64;
            int ty2c = (ty2 < NTT) ? ty2 : 0;
            const float4* tq = (const float4*)(Tq + x * TS);
            const float4* k0 = (const float4*)(Tk + ty0 * TS);
            const float4* k1 = (const float4*)(Tk + ty1 * TS);
            const float4* k2 = (const float4*)(Tk + ty2c * TS);
            float a0 = 0, a1 = 0, a2 = 0;
            #pragma unroll 8
            for (int o4 = 0; o4 < OO / 4; o4++) {
                float4 qv = tq[o4];
                float4 b0 = k0[o4];
                a0 += qv.x * b0.x + qv.y * b0.y + qv.z * b0.z + qv.w * b0.w;
                float4 b1 = k1[o4];
                a1 += qv.x * b1.x + qv.y * b1.y + qv.z * b1.z + qv.w * b1.w;
                float4 b2 = k2[o4];
                a2 += qv.x * b2.x + qv.y * b2.y + qv.z * b2.z + qv.w * b2.w;
            }
            __syncwarp();
            Gr[warp * 96 + ty0] = tanhf(a0);
            Gr[warp * 96 + ty1] = tanhf(a1);
            if (ty2 < NTT) Gr[warp * 96 + ty2] = tanhf(a2);
            __syncwarp();
            float o0 = 0, o1 = 0;
            for (int ty = 0; ty < NTT; ty++) {
                float g = Gr[warp * 96 + ty];
                o0 += g * vg[ty * EVD + lane];
                o1 += g * vg[ty * EVD + lane + 32];
            }
            size_t base = ((size_t)bh * NNN + 2 * x) * EVD;
            out[base + lane]            = o0;
            out[base + lane + 32]       = o1;
            out[base + EVD + lane]      = o0;
            out[base + EVD + lane + 32] = o1;
            if (x == 92) {
                size_t bl2 = ((size_t)bh * NNN + 186) * EVD;
                out[bl2 + lane]      = o0;
                out[bl2 + lane + 32] = o1;
            }
        }
    }
}

// ---------------------------------------------------------------------------
extern "C" void kernel_launch(void* const* d_in, const int* in_sizes, int n_in,
                              void* d_out, int out_size)
{
    const float* q   = (const float*)d_in[0];
    const float* k   = (const float*)d_in[1];
    const float* v   = (const float*)d_in[2];
    const float* Wq1 = (const float*)d_in[3];
    const float* bq1 = (const float*)d_in[4];
    const float* Wq2 = (const float*)d_in[5];
    const float* bq2 = (const float*)d_in[6];
    const float* Wk1 = (const float*)d_in[7];
    const float* bk1 = (const float*)d_in[8];
    const float* Wk2 = (const float*)d_in[9];
    const float* bk2 = (const float*)d_in[10];
    const float* Wlq = (const float*)d_in[11];
    const float* blq = (const float*)d_in[12];
    const float* Wlk = (const float*)d_in[13];
    const float* blk = (const float*)d_in[14];
    float* out = (float*)d_out;

    const int SM3 = (2 * NTT * TS + NTT * EVD + 8 * 96) * 4;
    static int attr_done = 0;
    if (!attr_done) {
        cudaFuncSetAttribute(k_proj, cudaFuncAttributeMaxDynamicSharedMemorySize, SM_TOT);
        cudaFuncSetAttribute(k_attn, cudaFuncAttributeMaxDynamicSharedMemorySize, SM3);
        attr_done = 1;
    }

    k_augment<<<dim3(8, 8), 256>>>(q, k, Wq1, bq1, Wq2, bq2, Wk1, bk1, Wk2, bk2);
    k_proj<<<dim3(256, 2), 256, SM_TOT>>>(Wlq, blq, Wlk, blk);
    k_attn<<<dim3(4, 2), 256, SM3>>>(v, out);
}

// round 5
// speedup vs baseline: 1.3751x; 1.3073x over previous
#include <cuda_runtime.h>
#include <cuda_bf16.h>
#include <mma.h>
#include <cstdint>
#include <math.h>

using namespace nvcuda;

#define CCH  192
#define LTT  94
#define NTT  93
#define NNN  187
#define OO   256
#define SIGD 37056
#define EVD  64

// A as bf16 hi/lo split, rows 94,95 zero. [w][head][96][192]
__device__ __nv_bfloat16 d_Ahi[2][4][96][CCH];
__device__ __nv_bfloat16 d_Alo[2][4][96][CCH];
__device__ float d_P[2][4][NTT][OO];      // projected signatures

__device__ __forceinline__ void split_bf16(float v, __nv_bfloat16& hi, __nv_bfloat16& lo) {
    hi = __float2bfloat16(v);
    lo = __float2bfloat16(v - __bfloat162float(hi));
}

// ---------------------------------------------------------------------------
// Kernel 1: augmentation -> d_Ahi/d_Alo   grid (8, 8), 256 thr
// W1/W2 cached in dynamic smem (81,664 B)
// ---------------------------------------------------------------------------
#define AUG_SMEM (12096 * 4 + 128 * 65 * 4)

__global__ __launch_bounds__(256) void k_augment(
    const float* __restrict__ qg, const float* __restrict__ kg,
    const float* __restrict__ Wq1, const float* __restrict__ bq1,
    const float* __restrict__ Wq2, const float* __restrict__ bq2,
    const float* __restrict__ Wk1, const float* __restrict__ bk1,
    const float* __restrict__ Wk2, const float* __restrict__ bk2)
{
    extern __shared__ float dyn[];
    float* W1s = dyn;                 // [64*189] linear (row stride 189)
    float* W2s = dyn + 12096;         // [128][65]
    __shared__ float xs[14][65];
    __shared__ float y1s[64][12];

    int wh = blockIdx.x;
    int w = wh >> 2, head = wh & 3;
    int b = head >> 1, h = head & 1;
    int t0 = blockIdx.y * 12;
    const float* x  = w ? kg  : qg;
    const float* W1 = w ? Wk1 : Wq1;
    const float* B1 = w ? bk1 : bq1;
    const float* W2 = w ? Wk2 : Wq2;
    const float* B2 = w ? bk2 : bq2;
    int tid = threadIdx.x;

    for (int g = tid; g < 12096; g += 256) W1s[g] = W1[g];
    for (int g = tid; g < 128 * 64; g += 256) {
        int c = g >> 6, j = g & 63;
        W2s[c * 65 + j] = W2[g];
    }
    for (int idx = tid; idx < 14 * 63; idx += 256) {
        int r = idx / 63, e = idx - r * 63;
        int l = t0 + r;
        if (l < 96) xs[r][e] = x[((b * 96 + l) * 2 + h) * 63 + e];
    }
    __syncthreads();

    // conv1: 3 independent accumulator chains
    for (int idx = tid; idx < 64 * 12; idx += 256) {
        int c = idx / 12, tl = idx - c * 12;
        int t = t0 + tl;
        float acc = 0.0f;
        if (t < LTT) {
            const float* wr = W1s + c * 189;
            float a0 = 0, a1 = 0, a2 = 0;
            #pragma unroll 9
            for (int e = 0; e < 63; e++) {
                a0 += wr[e * 3 + 0] * xs[tl][e];
                a1 += wr[e * 3 + 1] * xs[tl + 1][e];
                a2 += wr[e * 3 + 2] * xs[tl + 2][e];
            }
            acc = B1[c] + a0 + a1 + a2;
        }
        y1s[c][tl] = acc;
    }
    __syncthreads();

    // conv2 + relu -> channels 64..191 (bf16 hi/lo)
    for (int idx = tid; idx < 128 * 12; idx += 256) {
        int c = idx / 12, tl = idx - c * 12;
        int t = t0 + tl;
        if (t < LTT) {
            const float* wr = W2s + c * 65;
            float a0 = 0, a1 = 0;
            #pragma unroll
            for (int j = 0; j < 64; j += 2) {
                a0 += wr[j]     * y1s[j][tl];
                a1 += wr[j + 1] * y1s[j + 1][tl];
            }
            float v = fmaxf(B2[c] + a0 + a1, 0.0f);
            __nv_bfloat16 hi, lo;
            split_bf16(v, hi, lo);
            d_Ahi[w][head][t][64 + c] = hi;
            d_Alo[w][head][t][64 + c] = lo;
        }
    }
    // trunc (0..62) + time (63)
    for (int idx = tid; idx < 64 * 12; idx += 256) {
        int tl = idx >> 6, c = idx & 63;
        int t = t0 + tl;
        if (t < LTT) {
            float v = (c == 63) ? (t * (1.0f / 93.0f)) : xs[tl + 2][c];
            __nv_bfloat16 hi, lo;
            split_bf16(v, hi, lo);
            d_Ahi[w][head][t][c] = hi;
            d_Alo[w][head][t][c] = lo;
        }
    }
    // zero pad rows 94,95
    if (blockIdx.y == 7) {
        for (int idx = tid; idx < 2 * CCH; idx += 256) {
            int t = 94 + idx / CCH, c = idx % CCH;
            d_Ahi[w][head][t][c] = __float2bfloat16(0.0f);
            d_Alo[w][head][t][c] = __float2bfloat16(0.0f);
        }
    }
}

// ---------------------------------------------------------------------------
// Kernel 2: wmma bf16-split  Z = A @ W2half^T  + dots + scan + P
// grid (256, 2), 256 threads, ~201 KB dynamic smem, 1 CTA/SM
// ---------------------------------------------------------------------------
#define WS2 200   // bf16 row stride
#define DS  100   // fp32 row stride for D

#define OFF_WHI  0
#define OFF_WLO  38400
#define OFF_AHI  76800
#define OFF_ALO  115200
#define OFF_D    153600
#define OFF_W1   192000
#define OFF_ACC  192768    // [4 heads][5][96] (0=alpha 1=delta 2=beta 3=gamma 4=e)
#define OFF_PREF 200448
#define SM_TOT   200832

__global__ __launch_bounds__(256, 1) void k_proj(
    const float* __restrict__ Wlq, const float* __restrict__ blq,
    const float* __restrict__ Wlk, const float* __restrict__ blk)
{
    extern __shared__ char sm[];
    __nv_bfloat16* Whi = (__nv_bfloat16*)(sm + OFF_WHI);
    __nv_bfloat16* Wlo = (__nv_bfloat16*)(sm + OFF_WLO);
    __nv_bfloat16* Ahi = (__nv_bfloat16*)(sm + OFF_AHI);
    __nv_bfloat16* Alo = (__nv_bfloat16*)(sm + OFF_ALO);
    float* Dsh   = (float*)(sm + OFF_D);
    float* w1sh  = (float*)(sm + OFF_W1);
    float* accS  = (float*)(sm + OFF_ACC);
    float* prefS = (float*)(sm + OFF_PREF);

    int o = blockIdx.x, w = blockIdx.y;
    const float* Wl = w ? Wlk : Wlq;
    const float* bl = w ? blk : blq;
    int tid = threadIdx.x, lane = tid & 31, warp = tid >> 5;

    for (int g = tid; g < CCH; g += 256) w1sh[g] = Wl[(size_t)o * SIGD + g];
    float blo = bl[o];

    for (int half = 0; half < 2; half++) {
        // ---- W2 half -> bf16 hi/lo (only conversion left in this kernel) ----
        __syncthreads();
        const float* Wsrc = Wl + (size_t)o * SIGD + CCH + (size_t)half * 96 * CCH;
        for (int g = tid; g < 96 * CCH; g += 256) {
            int i = g / CCH, j = g - i * CCH;
            __nv_bfloat16 hi, lo;
            split_bf16(Wsrc[g], hi, lo);
            Whi[i * WS2 + j] = hi;
            Wlo[i * WS2 + j] = lo;
        }
        __syncthreads();

        for (int head = 0; head < 4; head++) {
            // ---- A hi/lo: straight vectorized copy from global bf16 ----
            const uint4* srcH = (const uint4*)&d_Ahi[w][head][0][0];
            const uint4* srcL = (const uint4*)&d_Alo[w][head][0][0];
            for (int g = tid; g < 96 * CCH / 8; g += 256) {
                int row = g / 24, c8 = g - row * 24;
                *(uint4*)&Ahi[row * WS2 + c8 * 8] = srcH[g];
                *(uint4*)&Alo[row * WS2 + c8 * 8] = srcL[g];
            }
            __syncthreads();

            // ---- MMA: D[96][96] = A[96x192] @ Whalf^T, 3 split passes ----
            for (int tt = warp; tt < 36; tt += 8) {
                int mt = tt / 6, nt = tt % 6;
                wmma::fragment<wmma::accumulator, 16, 16, 16, float> fc;
                wmma::fill_fragment(fc, 0.0f);
                #pragma unroll
                for (int k = 0; k < 12; k++) {
                    wmma::fragment<wmma::matrix_a, 16, 16, 16, __nv_bfloat16, wmma::row_major> fa_hi, fa_lo;
                    wmma::fragment<wmma::matrix_b, 16, 16, 16, __nv_bfloat16, wmma::col_major> fb_hi, fb_lo;
                    wmma::load_matrix_sync(fa_hi, Ahi + mt * 16 * WS2 + k * 16, WS2);
                    wmma::load_matrix_sync(fa_lo, Alo + mt * 16 * WS2 + k * 16, WS2);
                    wmma::load_matrix_sync(fb_hi, Whi + nt * 16 * WS2 + k * 16, WS2);
                    wmma::load_matrix_sync(fb_lo, Wlo + nt * 16 * WS2 + k * 16, WS2);
                    wmma::mma_sync(fc, fa_hi, fb_hi, fc);
                    wmma::mma_sync(fc, fa_hi, fb_lo, fc);
                    wmma::mma_sync(fc, fa_lo, fb_hi, fc);
                }
                wmma::store_matrix_sync(Dsh + mt * 16 * DS + nt * 16, fc, DS, wmma::mem_row_major);
            }
            __syncthreads();

            // ---- tridiagonal dots (+ e on half 0) ----
            for (int r = 0; r < 12; r++) {
                int t = warp * 12 + r;
                if (t >= LTT) continue;
                int tm1 = (t >= 1) ? t - 1 : 0;
                float pa = 0, pd = 0, pb = 0, pg = 0, pe = 0;
                #pragma unroll
                for (int m = 0; m < 3; m++) {
                    int il = lane + 32 * m;
                    int c = half * 96 + il;
                    float z = Dsh[t * DS + il];
                    float at  = __bfloat162float(Ahi[t * WS2 + c])       + __bfloat162float(Alo[t * WS2 + c]);
                    float a0  = __bfloat162float(Ahi[c])                 + __bfloat162float(Alo[c]);
                    float atm = __bfloat162float(Ahi[tm1 * WS2 + c])     + __bfloat162float(Alo[tm1 * WS2 + c]);
                    float atp = __bfloat162float(Ahi[(t + 1) * WS2 + c]) + __bfloat162float(Alo[(t + 1) * WS2 + c]);
                    pa += z * at; pd += z * a0; pb += z * atm; pg += z * atp;
                }
                if (half == 0) {
                    #pragma unroll
                    for (int m = 0; m < 6; m++) {
                        int j = lane + 32 * m;
                        pe += w1sh[j] * (__bfloat162float(Ahi[t * WS2 + j]) + __bfloat162float(Alo[t * WS2 + j]));
                    }
                }
                #pragma unroll
                for (int off = 16; off; off >>= 1) {
                    pa += __shfl_down_sync(0xffffffffu, pa, off);
                    pd += __shfl_down_sync(0xffffffffu, pd, off);
                    pb += __shfl_down_sync(0xffffffffu, pb, off);
                    pg += __shfl_down_sync(0xffffffffu, pg, off);
                    pe += __shfl_down_sync(0xffffffffu, pe, off);
                }
                if (lane == 0) {
                    float* acc = accS + head * 480;
                    if (half == 0) {
                        acc[0 * 96 + t] = pa;
                        acc[1 * 96 + t] = pd;
                        if (t >= 1)  acc[2 * 96 + t - 1] = pb;
                        if (t <= 92) acc[3 * 96 + t] = pg;
                        acc[4 * 96 + t] = pe;
                    } else {
                        acc[0 * 96 + t] += pa;
                        acc[1 * 96 + t] += pd;
                        if (t >= 1)  acc[2 * 96 + t - 1] += pb;
                        if (t <= 92) acc[3 * 96 + t] += pg;
                    }
                }
            }
            __syncthreads();
        }
    }

    // ---- per-head scan + P assembly ----
    for (int head = 0; head < 4; head++) {
        float* acc = accS + head * 480;
        if (warp == 0) {
            float carry = 0.0f;
            for (int ch = 0; ch < 3; ch++) {
                int idx = ch * 32 + lane;
                float vv = (idx < NTT) ? (acc[2 * 96 + idx] - acc[3 * 96 + idx]) : 0.0f;
                #pragma unroll
                for (int off = 1; off < 32; off <<= 1) {
                    float n = __shfl_up_sync(0xffffffffu, vv, off);
                    if (lane >= off) vv += n;
                }
                vv += carry;
                if (idx < NTT) prefS[idx] = vv;
                carry = __shfl_sync(0xffffffffu, vv, 31);
            }
        }
        __syncthreads();
        if (tid < NTT) {
            int t = tid;
            float Pv = blo + acc[4 * 96 + t + 1] - acc[4 * 96 + 0]
                     + 0.5f * (acc[0 * 96 + t + 1] + acc[0 * 96 + 0])
                     - acc[1 * 96 + t + 1]
                     + 0.5f * prefS[t];
            d_P[w][head][t][o] = Pv;
        }
        __syncthreads();
    }
}

// ---------------------------------------------------------------------------
// Kernel 3: attn = tanh(Pq @ Pk^T) on 93x93 core; out = attn @ v_agg
// grid (4, 4), 256 threads
// ---------------------------------------------------------------------------
#define TS 260

__global__ __launch_bounds__(256) void k_attn(
    const float* __restrict__ v, float* __restrict__ out)
{
    extern __shared__ float sm3[];
    float* Tq = sm3;
    float* Tk = Tq + NTT * TS;
    float* vg = Tk + NTT * TS;
    float* Gr = vg + NTT * EVD;

    int bh = blockIdx.x, zh = blockIdx.y;
    int tid = threadIdx.x, lane = tid & 31, warp = tid >> 5;

    for (int g = tid; g < NTT * OO; g += 256) {
        int t = g >> 8, o = g & 255;
        Tq[t * TS + o] = d_P[0][bh][t][o];
        Tk[t * TS + o] = d_P[1][bh][t][o];
    }
    for (int g = tid; g < NTT * EVD; g += 256) {
        int t = g >> 6, e = g & 63;
        float s = v[((size_t)bh * NNN + 2 * t) * EVD + e]
                + v[((size_t)bh * NNN + 2 * t + 1) * EVD + e];
        if (t == 92) s += v[((size_t)bh * NNN + 186) * EVD + e];
        vg[g] = s;
    }
    __syncthreads();

    int x0 = zh * 24;
    for (int xx = 0; xx < 3; xx++) {
        int x = x0 + warp + 8 * xx;
        if (x < NTT) {
            int ty0 = lane, ty1 = lane + 32, ty2 = lane + 64;
            int ty2c = (ty2 < NTT) ? ty2 : 0;
            const float4* tq = (const float4*)(Tq + x * TS);
            const float4* k0 = (const float4*)(Tk + ty0 * TS);
            const float4* k1 = (const float4*)(Tk + ty1 * TS);
            const float4* k2 = (const float4*)(Tk + ty2c * TS);
            float a0 = 0, a1 = 0, a2 = 0;
            #pragma unroll 8
            for (int o4 = 0; o4 < OO / 4; o4++) {
                float4 qv = tq[o4];
                float4 b0 = k0[o4];
                a0 += qv.x * b0.x + qv.y * b0.y + qv.z * b0.z + qv.w * b0.w;
                float4 b1 = k1[o4];
                a1 += qv.x * b1.x + qv.y * b1.y + qv.z * b1.z + qv.w * b1.w;
                float4 b2 = k2[o4];
                a2 += qv.x * b2.x + qv.y * b2.y + qv.z * b2.z + qv.w * b2.w;
            }
            __syncwarp();
            Gr[warp * 96 + ty0] = tanhf(a0);
            Gr[warp * 96 + ty1] = tanhf(a1);
            if (ty2 < NTT) Gr[warp * 96 + ty2] = tanhf(a2);
            __syncwarp();
            float o0 = 0, o1 = 0;
            for (int ty = 0; ty < NTT; ty++) {
                float g = Gr[warp * 96 + ty];
                o0 += g * vg[ty * EVD + lane];
                o1 += g * vg[ty * EVD + lane + 32];
            }
            size_t base = ((size_t)bh * NNN + 2 * x) * EVD;
            out[base + lane]            = o0;
            out[base + lane + 32]       = o1;
            out[base + EVD + lane]      = o0;
            out[base + EVD + lane + 32] = o1;
            if (x == 92) {
                size_t bl2 = ((size_t)bh * NNN + 186) * EVD;
                out[bl2 + lane]      = o0;
                out[bl2 + lane + 32] = o1;
            }
        }
    }
}

// ---------------------------------------------------------------------------
extern "C" void kernel_launch(void* const* d_in, const int* in_sizes, int n_in,
                              void* d_out, int out_size)
{
    const float* q   = (const float*)d_in[0];
    const float* k   = (const float*)d_in[1];
    const float* v   = (const float*)d_in[2];
    const float* Wq1 = (const float*)d_in[3];
    const float* bq1 = (const float*)d_in[4];
    const float* Wq2 = (const float*)d_in[5];
    const float* bq2 = (const float*)d_in[6];
    const float* Wk1 = (const float*)d_in[7];
    const float* bk1 = (const float*)d_in[8];
    const float* Wk2 = (const float*)d_in[9];
    const float* bk2 = (const float*)d_in[10];
    const float* Wlq = (const float*)d_in[11];
    const float* blq = (const float*)d_in[12];
    const float* Wlk = (const float*)d_in[13];
    const float* blk = (const float*)d_in[14];
    float* out = (float*)d_out;

    const int SM3 = (2 * NTT * TS + NTT * EVD + 8 * 96) * 4;
    static int attr_done = 0;
    if (!attr_done) {
        cudaFuncSetAttribute(k_augment, cudaFuncAttributeMaxDynamicSharedMemorySize, AUG_SMEM);
        cudaFuncSetAttribute(k_proj, cudaFuncAttributeMaxDynamicSharedMemorySize, SM_TOT);
        cudaFuncSetAttribute(k_attn, cudaFuncAttributeMaxDynamicSharedMemorySize, SM3);
        attr_done = 1;
    }

    k_augment<<<dim3(8, 8), 256, AUG_SMEM>>>(q, k, Wq1, bq1, Wq2, bq2, Wk1, bk1, Wk2, bk2);
    k_proj<<<dim3(256, 2), 256, SM_TOT>>>(Wlq, blq, Wlk, blk);
    k_attn<<<dim3(4, 4), 256, SM3>>>(v, out);
}

// round 6
// speedup vs baseline: 1.8462x; 1.3426x over previous
#include <cuda_runtime.h>
#include <cuda_bf16.h>
#include <cstdint>
#include <math.h>

#define CCH  192
#define LTT  94
#define NTT  93
#define NNN  187
#define OO   256
#define SIGD 37056
#define EVD  64

// A as bf16 hi/lo split, rows 94,95 zero. [w][head][96][192]
__device__ __nv_bfloat16 d_Ahi[2][4][96][CCH];
__device__ __nv_bfloat16 d_Alo[2][4][96][CCH];
__device__ float d_P[2][4][NTT][OO];      // projected signatures

__device__ __forceinline__ void split_bf16(float v, __nv_bfloat16& hi, __nv_bfloat16& lo) {
    hi = __float2bfloat16(v);
    lo = __float2bfloat16(v - __bfloat162float(hi));
}
__device__ __forceinline__ uint32_t smem_u32(const void* p) {
    uint32_t a;
    asm("{ .reg .u64 t; cvta.to.shared.u64 t, %1; cvt.u32.u64 %0, t; }" : "=r"(a) : "l"(p));
    return a;
}
__device__ __forceinline__ void ldsm_x4(uint32_t* r, uint32_t addr) {
    asm volatile("ldmatrix.sync.aligned.m8n8.x4.shared.b16 {%0,%1,%2,%3}, [%4];"
        : "=r"(r[0]), "=r"(r[1]), "=r"(r[2]), "=r"(r[3]) : "r"(addr));
}
__device__ __forceinline__ void ldsm_x2(uint32_t* r, uint32_t addr) {
    asm volatile("ldmatrix.sync.aligned.m8n8.x2.shared.b16 {%0,%1}, [%2];"
        : "=r"(r[0]), "=r"(r[1]) : "r"(addr));
}
__device__ __forceinline__ void mma16816(float* c, const uint32_t* a, const uint32_t* b) {
    asm volatile("mma.sync.aligned.m16n8k16.row.col.f32.bf16.bf16.f32 "
        "{%0,%1,%2,%3}, {%4,%5,%6,%7}, {%8,%9}, {%0,%1,%2,%3};"
        : "+f"(c[0]), "+f"(c[1]), "+f"(c[2]), "+f"(c[3])
        : "r"(a[0]), "r"(a[1]), "r"(a[2]), "r"(a[3]), "r"(b[0]), "r"(b[1]));
}

// ---------------------------------------------------------------------------
// Kernel 1: augmentation -> d_Ahi/d_Alo   grid (8, 8), 256 thr
// ---------------------------------------------------------------------------
#define AUG_SMEM (12096 * 4 + 128 * 65 * 4)

__global__ __launch_bounds__(256) void k_augment(
    const float* __restrict__ qg, const float* __restrict__ kg,
    const float* __restrict__ Wq1, const float* __restrict__ bq1,
    const float* __restrict__ Wq2, const float* __restrict__ bq2,
    const float* __restrict__ Wk1, const float* __restrict__ bk1,
    const float* __restrict__ Wk2, const float* __restrict__ bk2)
{
    extern __shared__ float dyn[];
    float* W1s = dyn;                 // [64*189] linear
    float* W2s = dyn + 12096;         // [128][65]
    __shared__ float xs[14][65];
    __shared__ float y1s[64][12];

    int wh = blockIdx.x;
    int w = wh >> 2, head = wh & 3;
    int b = head >> 1, h = head & 1;
    int t0 = blockIdx.y * 12;
    const float* x  = w ? kg  : qg;
    const float* W1 = w ? Wk1 : Wq1;
    const float* B1 = w ? bk1 : bq1;
    const float* W2 = w ? Wk2 : Wq2;
    const float* B2 = w ? bk2 : bq2;
    int tid = threadIdx.x;

    const float4* W1v = (const float4*)W1;
    for (int g = tid; g < 3024; g += 256) ((float4*)W1s)[g] = W1v[g];
    const float4* W2v = (const float4*)W2;
    for (int g = tid; g < 2048; g += 256) {
        float4 vv = W2v[g];
        int c = (g * 4) >> 6, j = (g * 4) & 63;
        float* dst = W2s + c * 65 + j;
        dst[0] = vv.x; dst[1] = vv.y; dst[2] = vv.z; dst[3] = vv.w;
    }
    for (int idx = tid; idx < 14 * 63; idx += 256) {
        int r = idx / 63, e = idx - r * 63;
        int l = t0 + r;
        if (l < 96) xs[r][e] = x[((b * 96 + l) * 2 + h) * 63 + e];
    }
    __syncthreads();

    for (int idx = tid; idx < 64 * 12; idx += 256) {
        int c = idx / 12, tl = idx - c * 12;
        int t = t0 + tl;
        float acc = 0.0f;
        if (t < LTT) {
            const float* wr = W1s + c * 189;
            float a0 = 0, a1 = 0, a2 = 0;
            #pragma unroll 9
            for (int e = 0; e < 63; e++) {
                a0 += wr[e * 3 + 0] * xs[tl][e];
                a1 += wr[e * 3 + 1] * xs[tl + 1][e];
                a2 += wr[e * 3 + 2] * xs[tl + 2][e];
            }
            acc = B1[c] + a0 + a1 + a2;
        }
        y1s[c][tl] = acc;
    }
    __syncthreads();

    for (int idx = tid; idx < 128 * 12; idx += 256) {
        int c = idx / 12, tl = idx - c * 12;
        int t = t0 + tl;
        if (t < LTT) {
            const float* wr = W2s + c * 65;
            float a0 = 0, a1 = 0;
            #pragma unroll
            for (int j = 0; j < 64; j += 2) {
                a0 += wr[j]     * y1s[j][tl];
                a1 += wr[j + 1] * y1s[j + 1][tl];
            }
            float v = fmaxf(B2[c] + a0 + a1, 0.0f);
            __nv_bfloat16 hi, lo;
            split_bf16(v, hi, lo);
            d_Ahi[w][head][t][64 + c] = hi;
            d_Alo[w][head][t][64 + c] = lo;
        }
    }
    for (int idx = tid; idx < 64 * 12; idx += 256) {
        int tl = idx >> 6, c = idx & 63;
        int t = t0 + tl;
        if (t < LTT) {
            float v = (c == 63) ? (t * (1.0f / 93.0f)) : xs[tl + 2][c];
            __nv_bfloat16 hi, lo;
            split_bf16(v, hi, lo);
            d_Ahi[w][head][t][c] = hi;
            d_Alo[w][head][t][c] = lo;
        }
    }
    if (blockIdx.y == 7) {
        for (int idx = tid; idx < 2 * CCH; idx += 256) {
            int t = 94 + idx / CCH, c = idx % CCH;
            d_Ahi[w][head][t][c] = __float2bfloat16(0.0f);
            d_Alo[w][head][t][c] = __float2bfloat16(0.0f);
        }
    }
}

// ---------------------------------------------------------------------------
// Kernel 2: raw-mma bf16-split  Z = A @ W2half^T  + dots + scan + P
// grid (256, 2), 256 threads, ~201 KB dynamic smem, 1 CTA/SM
// ---------------------------------------------------------------------------
#define WS2 200   // bf16 row stride (400 B)
#define DS  100   // fp32 row stride for D

#define OFF_WHI  0
#define OFF_WLO  38400
#define OFF_AHI  76800
#define OFF_ALO  115200
#define OFF_D    153600
#define OFF_W1   192000
#define OFF_ACC  192768    // [4 heads][5][96]
#define OFF_PREF 200448
#define SM_TOT   200832

__global__ __launch_bounds__(256, 1) void k_proj(
    const float* __restrict__ Wlq, const float* __restrict__ blq,
    const float* __restrict__ Wlk, const float* __restrict__ blk)
{
    extern __shared__ char sm[];
    __nv_bfloat16* Whi = (__nv_bfloat16*)(sm + OFF_WHI);
    __nv_bfloat16* Wlo = (__nv_bfloat16*)(sm + OFF_WLO);
    __nv_bfloat16* Ahi = (__nv_bfloat16*)(sm + OFF_AHI);
    __nv_bfloat16* Alo = (__nv_bfloat16*)(sm + OFF_ALO);
    float* Dsh   = (float*)(sm + OFF_D);
    float* w1sh  = (float*)(sm + OFF_W1);
    float* accS  = (float*)(sm + OFF_ACC);
    float* prefS = (float*)(sm + OFF_PREF);

    int o = blockIdx.x, w = blockIdx.y;
    const float* Wl = w ? Wlk : Wlq;
    const float* bl = w ? blk : blq;
    int tid = threadIdx.x, lane = tid & 31, warp = tid >> 5;
    int wm = warp >> 2, wn = warp & 3;   // 2 x 4 warp grid over D 96x96

    uint32_t aHiB = smem_u32(Ahi), aLoB = smem_u32(Alo);
    uint32_t wHiB = smem_u32(Whi), wLoB = smem_u32(Wlo);

    for (int g = tid; g < CCH; g += 256) w1sh[g] = Wl[(size_t)o * SIGD + g];
    float blo = bl[o];

    for (int half = 0; half < 2; half++) {
        // ---- W2 half -> bf16 hi/lo (vectorized) ----
        __syncthreads();
        const float4* Wsrc = (const float4*)(Wl + (size_t)o * SIGD + CCH + (size_t)half * 96 * CCH);
        for (int g = tid; g < 4608; g += 256) {
            float4 vv = Wsrc[g];
            int e0 = g * 4;
            int i = e0 / CCH, j = e0 - i * CCH;
            __nv_bfloat16 h0, l0, h1, l1, h2, l2, h3, l3;
            split_bf16(vv.x, h0, l0); split_bf16(vv.y, h1, l1);
            split_bf16(vv.z, h2, l2); split_bf16(vv.w, h3, l3);
            __nv_bfloat162 hp0, hp1, lp0, lp1;
            hp0.x = h0; hp0.y = h1; hp1.x = h2; hp1.y = h3;
            lp0.x = l0; lp0.y = l1; lp1.x = l2; lp1.y = l3;
            uint2 hu, lu;
            hu.x = *(uint32_t*)&hp0; hu.y = *(uint32_t*)&hp1;
            lu.x = *(uint32_t*)&lp0; lu.y = *(uint32_t*)&lp1;
            *(uint2*)&Whi[i * WS2 + j] = hu;
            *(uint2*)&Wlo[i * WS2 + j] = lu;
        }
        __syncthreads();

        for (int head = 0; head < 4; head++) {
            // ---- A hi/lo copy (uint4) ----
            const uint4* srcH = (const uint4*)&d_Ahi[w][head][0][0];
            const uint4* srcL = (const uint4*)&d_Alo[w][head][0][0];
            for (int g = tid; g < 96 * CCH / 8; g += 256) {
                int row = g / 24, c8 = g - row * 24;
                *(uint4*)&Ahi[row * WS2 + c8 * 8] = srcH[g];
                *(uint4*)&Alo[row * WS2 + c8 * 8] = srcL[g];
            }
            __syncthreads();

            // ---- raw mma: D = A @ Whalf^T, 3 split passes, reg-blocked ----
            {
                float acc[3][3][4];
                #pragma unroll
                for (int mt = 0; mt < 3; mt++)
                    #pragma unroll
                    for (int nt = 0; nt < 3; nt++)
                        #pragma unroll
                        for (int e = 0; e < 4; e++) acc[mt][nt][e] = 0.0f;

                // ldmatrix lane addressing offsets
                uint32_t aRow = 48 * wm + (lane & 15);
                uint32_t aColHalf = (lane >> 4) * 16;              // bytes
                uint32_t bRow = 24 * wn + (lane & 7);
                uint32_t bColHalf = ((lane >> 3) & 1) * 16;        // bytes

                #pragma unroll
                for (int k = 0; k < 12; k++) {
                    uint32_t kb = k * 32;  // 16 bf16 = 32 bytes
                    uint32_t ah[3][4], al[3][4], bh[3][2], blr[3][2];
                    #pragma unroll
                    for (int mt = 0; mt < 3; mt++) {
                        uint32_t off = (aRow + 16u * mt) * 400u + kb + aColHalf;
                        ldsm_x4(ah[mt], aHiB + off);
                        ldsm_x4(al[mt], aLoB + off);
                    }
                    #pragma unroll
                    for (int nt = 0; nt < 3; nt++) {
                        uint32_t off = (bRow + 8u * nt) * 400u + kb + bColHalf;
                        ldsm_x2(bh[nt],  wHiB + off);
                        ldsm_x2(blr[nt], wLoB + off);
                    }
                    #pragma unroll
                    for (int mt = 0; mt < 3; mt++)
                        #pragma unroll
                        for (int nt = 0; nt < 3; nt++) {
                            mma16816(acc[mt][nt], ah[mt], bh[nt]);
                            mma16816(acc[mt][nt], ah[mt], blr[nt]);
                            mma16816(acc[mt][nt], al[mt], bh[nt]);
                        }
                }
                // store D
                int r0 = 48 * wm + (lane >> 2);
                int c0 = 24 * wn + 2 * (lane & 3);
                #pragma unroll
                for (int mt = 0; mt < 3; mt++)
                    #pragma unroll
                    for (int nt = 0; nt < 3; nt++) {
                        float2 v0; v0.x = acc[mt][nt][0]; v0.y = acc[mt][nt][1];
                        float2 v1; v1.x = acc[mt][nt][2]; v1.y = acc[mt][nt][3];
                        *(float2*)&Dsh[(r0 + 16 * mt) * DS + c0 + 8 * nt]     = v0;
                        *(float2*)&Dsh[(r0 + 16 * mt + 8) * DS + c0 + 8 * nt] = v1;
                    }
            }
            __syncthreads();

            // ---- tridiagonal dots (+ e on half 0), vectorized ----
            for (int r = 0; r < 12; r++) {
                int t = warp * 12 + r;
                if (t >= LTT) continue;
                int tm1 = (t >= 1) ? t - 1 : 0;
                int tp1 = t + 1;
                float pa = 0, pd = 0, pb = 0, pg = 0, pe = 0;
                #pragma unroll
                for (int ch = 0; ch < 2; ch++) {
                    int wd = ch * 32 + lane;     // bf16x2 word index, i = 2*wd
                    if (ch == 1 && lane >= 16) break;
                    float2 zd = *(float2*)&Dsh[t * DS + 2 * wd];
                    __nv_bfloat162 h, l;
                    h = *(__nv_bfloat162*)&Ahi[t * WS2 + half * 96 + 2 * wd];
                    l = *(__nv_bfloat162*)&Alo[t * WS2 + half * 96 + 2 * wd];
                    float2 at; at.x = __bfloat162float(h.x) + __bfloat162float(l.x);
                               at.y = __bfloat162float(h.y) + __bfloat162float(l.y);
                    h = *(__nv_bfloat162*)&Ahi[half * 96 + 2 * wd];
                    l = *(__nv_bfloat162*)&Alo[half * 96 + 2 * wd];
                    float2 a0; a0.x = __bfloat162float(h.x) + __bfloat162float(l.x);
                               a0.y = __bfloat162float(h.y) + __bfloat162float(l.y);
                    h = *(__nv_bfloat162*)&Ahi[tm1 * WS2 + half * 96 + 2 * wd];
                    l = *(__nv_bfloat162*)&Alo[tm1 * WS2 + half * 96 + 2 * wd];
                    float2 am; am.x = __bfloat162float(h.x) + __bfloat162float(l.x);
                               am.y = __bfloat162float(h.y) + __bfloat162float(l.y);
                    h = *(__nv_bfloat162*)&Ahi[tp1 * WS2 + half * 96 + 2 * wd];
                    l = *(__nv_bfloat162*)&Alo[tp1 * WS2 + half * 96 + 2 * wd];
                    float2 ap; ap.x = __bfloat162float(h.x) + __bfloat162float(l.x);
                               ap.y = __bfloat162float(h.y) + __bfloat162float(l.y);
                    pa += zd.x * at.x + zd.y * at.y;
                    pd += zd.x * a0.x + zd.y * a0.y;
                    pb += zd.x * am.x + zd.y * am.y;
                    pg += zd.x * ap.x + zd.y * ap.y;
                    if (half == 0) {
                        // e: full 192-dot with w1 (only once)
                        float2 w1a = *(float2*)&w1sh[2 * wd];
                        float2 w1b = *(float2*)&w1sh[96 + 2 * wd];
                        __nv_bfloat162 h2 = *(__nv_bfloat162*)&Ahi[t * WS2 + 96 + 2 * wd];
                        __nv_bfloat162 l2 = *(__nv_bfloat162*)&Alo[t * WS2 + 96 + 2 * wd];
                        pe += w1a.x * at.x + w1a.y * at.y;   // wrong pairing fix below
                        pe += w1b.x * (__bfloat162float(h2.x) + __bfloat162float(l2.x))
                            + w1b.y * (__bfloat162float(h2.y) + __bfloat162float(l2.y));
                    }
                }
                #pragma unroll
                for (int off = 16; off; off >>= 1) {
                    pa += __shfl_down_sync(0xffffffffu, pa, off);
                    pd += __shfl_down_sync(0xffffffffu, pd, off);
                    pb += __shfl_down_sync(0xffffffffu, pb, off);
                    pg += __shfl_down_sync(0xffffffffu, pg, off);
                    pe += __shfl_down_sync(0xffffffffu, pe, off);
                }
                if (lane == 0) {
                    float* acc = accS + head * 480;
                    if (half == 0) {
                        acc[0 * 96 + t] = pa;
                        acc[1 * 96 + t] = pd;
                        if (t >= 1)  acc[2 * 96 + t - 1] = pb;
                        if (t <= 92) acc[3 * 96 + t] = pg;
                        acc[4 * 96 + t] = pe;
                    } else {
                        acc[0 * 96 + t] += pa;
                        acc[1 * 96 + t] += pd;
                        if (t >= 1)  acc[2 * 96 + t - 1] += pb;
                        if (t <= 92) acc[3 * 96 + t] += pg;
                    }
                }
            }
            __syncthreads();
        }
    }

    // ---- per-head scan + P assembly ----
    for (int head = 0; head < 4; head++) {
        float* acc = accS + head * 480;
        if (warp == 0) {
            float carry = 0.0f;
            for (int ch = 0; ch < 3; ch++) {
                int idx = ch * 32 + lane;
                float vv = (idx < NTT) ? (acc[2 * 96 + idx] - acc[3 * 96 + idx]) : 0.0f;
                #pragma unroll
                for (int off = 1; off < 32; off <<= 1) {
                    float n = __shfl_up_sync(0xffffffffu, vv, off);
                    if (lane >= off) vv += n;
                }
                vv += carry;
                if (idx < NTT) prefS[idx] = vv;
                carry = __shfl_sync(0xffffffffu, vv, 31);
            }
        }
        __syncthreads();
        if (tid < NTT) {
            int t = tid;
            float Pv = blo + acc[4 * 96 + t + 1] - acc[4 * 96 + 0]
                     + 0.5f * (acc[0 * 96 + t + 1] + acc[0 * 96 + 0])
                     - acc[1 * 96 + t + 1]
                     + 0.5f * prefS[t];
            d_P[w][head][t][o] = Pv;
        }
        __syncthreads();
    }
}

// ---------------------------------------------------------------------------
// Kernel 3: attn = tanh(Pq @ Pk^T) on 93x93 core; out = attn @ v_agg
// ---------------------------------------------------------------------------
#define TS 260

__global__ __launch_bounds__(256) void k_attn(
    const float* __restrict__ v, float* __restrict__ out)
{
    extern __shared__ float sm3[];
    float* Tq = sm3;
    float* Tk = Tq + NTT * TS;
    float* vg = Tk + NTT * TS;
    float* Gr = vg + NTT * EVD;

    int bh = blockIdx.x, zh = blockIdx.y;
    int tid = threadIdx.x, lane = tid & 31, warp = tid >> 5;

    for (int g = tid; g < NTT * OO; g += 256) {
        int t = g >> 8, o = g & 255;
        Tq[t * TS + o] = d_P[0][bh][t][o];
        Tk[t * TS + o] = d_P[1][bh][t][o];
    }
    for (int g = tid; g < NTT * EVD; g += 256) {
        int t = g >> 6, e = g & 63;
        float s = v[((size_t)bh * NNN + 2 * t) * EVD + e]
                + v[((size_t)bh * NNN + 2 * t + 1) * EVD + e];
        if (t == 92) s += v[((size_t)bh * NNN + 186) * EVD + e];
        vg[g] = s;
    }
    __syncthreads();

    int x0 = zh * 24;
    for (int xx = 0; xx < 3; xx++) {
        int x = x0 + warp + 8 * xx;
        if (x < NTT) {
            int ty0 = lane, ty1 = lane + 32, ty2 = lane + 64;
            int ty2c = (ty2 < NTT) ? ty2 : 0;
            const float4* tq = (const float4*)(Tq + x * TS);
            const float4* k0 = (const float4*)(Tk + ty0 * TS);
            const float4* k1 = (const float4*)(Tk + ty1 * TS);
            const float4* k2 = (const float4*)(Tk + ty2c * TS);
            float a0 = 0, a1 = 0, a2 = 0;
            #pragma unroll 8
            for (int o4 = 0; o4 < OO / 4; o4++) {
                float4 qv = tq[o4];
                float4 b0 = k0[o4];
                a0 += qv.x * b0.x + qv.y * b0.y + qv.z * b0.z + qv.w * b0.w;
                float4 b1 = k1[o4];
                a1 += qv.x * b1.x + qv.y * b1.y + qv.z * b1.z + qv.w * b1.w;
                float4 b2 = k2[o4];
                a2 += qv.x * b2.x + qv.y * b2.y + qv.z * b2.z + qv.w * b2.w;
            }
            __syncwarp();
            Gr[warp * 96 + ty0] = tanhf(a0);
            Gr[warp * 96 + ty1] = tanhf(a1);
            if (ty2 < NTT) Gr[warp * 96 + ty2] = tanhf(a2);
            __syncwarp();
            float o0 = 0, o1 = 0;
            for (int ty = 0; ty < NTT; ty++) {
                float g = Gr[warp * 96 + ty];
                o0 += g * vg[ty * EVD + lane];
                o1 += g * vg[ty * EVD + lane + 32];
            }
            size_t base = ((size_t)bh * NNN + 2 * x) * EVD;
            out[base + lane]            = o0;
            out[base + lane + 32]       = o1;
            out[base + EVD + lane]      = o0;
            out[base + EVD + lane + 32] = o1;
            if (x == 92) {
                size_t bl2 = ((size_t)bh * NNN + 186) * EVD;
                out[bl2 + lane]      = o0;
                out[bl2 + lane + 32] = o1;
            }
        }
    }
}

// ---------------------------------------------------------------------------
extern "C" void kernel_launch(void* const* d_in, const int* in_sizes, int n_in,
                              void* d_out, int out_size)
{
    const float* q   = (const float*)d_in[0];
    const float* k   = (const float*)d_in[1];
    const float* v   = (const float*)d_in[2];
    const float* Wq1 = (const float*)d_in[3];
    const float* bq1 = (const float*)d_in[4];
    const float* Wq2 = (const float*)d_in[5];
    const float* bq2 = (const float*)d_in[6];
    const float* Wk1 = (const float*)d_in[7];
    const float* bk1 = (const float*)d_in[8];
    const float* Wk2 = (const float*)d_in[9];
    const float* bk2 = (const float*)d_in[10];
    const float* Wlq = (const float*)d_in[11];
    const float* blq = (const float*)d_in[12];
    const float* Wlk = (const float*)d_in[13];
    const float* blk = (const float*)d_in[14];
    float* out = (float*)d_out;

    const int SM3 = (2 * NTT * TS + NTT * EVD + 8 * 96) * 4;
    static int attr_done = 0;
    if (!attr_done) {
        cudaFuncSetAttribute(k_augment, cudaFuncAttributeMaxDynamicSharedMemorySize, AUG_SMEM);
        cudaFuncSetAttribute(k_proj, cudaFuncAttributeMaxDynamicSharedMemorySize, SM_TOT);
        cudaFuncSetAttribute(k_attn, cudaFuncAttributeMaxDynamicSharedMemorySize, SM3);
        attr_done = 1;
    }

    k_augment<<<dim3(8, 8), 256, AUG_SMEM>>>(q, k, Wq1, bq1, Wq2, bq2, Wk1, bk1, Wk2, bk2);
    k_proj<<<dim3(256, 2), 256, SM_TOT>>>(Wlq, blq, Wlk, blk);
    k_attn<<<dim3(4, 4), 256, SM3>>>(v, out);
}

// round 7
// speedup vs baseline: 2.1040x; 1.1396x over previous
#include <cuda_runtime.h>
#include <cuda_bf16.h>
#include <cstdint>
#include <math.h>

#define CCH  192
#define LTT  94
#define NTT  93
#define NNN  187
#define OO   256
#define SIGD 37056
#define EVD  64

// A as bf16 hi/lo split, rows 94,95 zero. [w][head][96][192]
__device__ __nv_bfloat16 d_Ahi[2][4][96][CCH];
__device__ __nv_bfloat16 d_Alo[2][4][96][CCH];
__device__ float d_P[2][4][NTT][OO];      // projected signatures

__device__ __forceinline__ void split_bf16(float v, __nv_bfloat16& hi, __nv_bfloat16& lo) {
    hi = __float2bfloat16(v);
    lo = __float2bfloat16(v - __bfloat162float(hi));
}
__device__ __forceinline__ uint32_t smem_u32(const void* p) {
    uint32_t a;
    asm("{ .reg .u64 t; cvta.to.shared.u64 t, %1; cvt.u32.u64 %0, t; }" : "=r"(a) : "l"(p));
    return a;
}
__device__ __forceinline__ void ldsm_x4(uint32_t* r, uint32_t addr) {
    asm volatile("ldmatrix.sync.aligned.m8n8.x4.shared.b16 {%0,%1,%2,%3}, [%4];"
        : "=r"(r[0]), "=r"(r[1]), "=r"(r[2]), "=r"(r[3]) : "r"(addr));
}
__device__ __forceinline__ void ldsm_x2(uint32_t* r, uint32_t addr) {
    asm volatile("ldmatrix.sync.aligned.m8n8.x2.shared.b16 {%0,%1}, [%2];"
        : "=r"(r[0]), "=r"(r[1]) : "r"(addr));
}
__device__ __forceinline__ void mma16816(float* c, const uint32_t* a, const uint32_t* b) {
    asm volatile("mma.sync.aligned.m16n8k16.row.col.f32.bf16.bf16.f32 "
        "{%0,%1,%2,%3}, {%4,%5,%6,%7}, {%8,%9}, {%0,%1,%2,%3};"
        : "+f"(c[0]), "+f"(c[1]), "+f"(c[2]), "+f"(c[3])
        : "r"(a[0]), "r"(a[1]), "r"(a[2]), "r"(a[3]), "r"(b[0]), "r"(b[1]));
}

// ---------------------------------------------------------------------------
// Kernel 1: augmentation -> d_Ahi/d_Alo   grid (8, 16), 256 thr
// ---------------------------------------------------------------------------
#define AUG_SMEM (12096 * 4 + 128 * 65 * 4)

__global__ __launch_bounds__(256) void k_augment(
    const float* __restrict__ qg, const float* __restrict__ kg,
    const float* __restrict__ Wq1, const float* __restrict__ bq1,
    const float* __restrict__ Wq2, const float* __restrict__ bq2,
    const float* __restrict__ Wk1, const float* __restrict__ bk1,
    const float* __restrict__ Wk2, const float* __restrict__ bk2)
{
    extern __shared__ float dyn[];
    float* W1s = dyn;                 // [64*189] linear
    float* W2s = dyn + 12096;         // [128][65]
    __shared__ float xs[8][65];
    __shared__ float y1s[64][6];

    int wh = blockIdx.x;
    int w = wh >> 2, head = wh & 3;
    int b = head >> 1, h = head & 1;
    int t0 = blockIdx.y * 6;
    const float* x  = w ? kg  : qg;
    const float* W1 = w ? Wk1 : Wq1;
    const float* B1 = w ? bk1 : bq1;
    const float* W2 = w ? Wk2 : Wq2;
    const float* B2 = w ? bk2 : bq2;
    int tid = threadIdx.x;

    const float4* W1v = (const float4*)W1;
    for (int g = tid; g < 3024; g += 256) ((float4*)W1s)[g] = W1v[g];
    const float4* W2v = (const float4*)W2;
    for (int g = tid; g < 2048; g += 256) {
        float4 vv = W2v[g];
        int c = (g * 4) >> 6, j = (g * 4) & 63;
        float* dst = W2s + c * 65 + j;
        dst[0] = vv.x; dst[1] = vv.y; dst[2] = vv.z; dst[3] = vv.w;
    }
    for (int idx = tid; idx < 8 * 63; idx += 256) {
        int r = idx / 63, e = idx - r * 63;
        int l = t0 + r;
        if (l < 96) xs[r][e] = x[((b * 96 + l) * 2 + h) * 63 + e];
    }
    __syncthreads();

    for (int idx = tid; idx < 64 * 6; idx += 256) {
        int c = idx / 6, tl = idx - c * 6;
        int t = t0 + tl;
        float acc = 0.0f;
        if (t < LTT) {
            const float* wr = W1s + c * 189;
            float a0 = 0, a1 = 0, a2 = 0;
            #pragma unroll 9
            for (int e = 0; e < 63; e++) {
                a0 += wr[e * 3 + 0] * xs[tl][e];
                a1 += wr[e * 3 + 1] * xs[tl + 1][e];
                a2 += wr[e * 3 + 2] * xs[tl + 2][e];
            }
            acc = B1[c] + a0 + a1 + a2;
        }
        y1s[c][tl] = acc;
    }
    __syncthreads();

    for (int idx = tid; idx < 128 * 6; idx += 256) {
        int c = idx / 6, tl = idx - c * 6;
        int t = t0 + tl;
        if (t < LTT) {
            const float* wr = W2s + c * 65;
            float a0 = 0, a1 = 0;
            #pragma unroll
            for (int j = 0; j < 64; j += 2) {
                a0 += wr[j]     * y1s[j][tl];
                a1 += wr[j + 1] * y1s[j + 1][tl];
            }
            float v = fmaxf(B2[c] + a0 + a1, 0.0f);
            __nv_bfloat16 hi, lo;
            split_bf16(v, hi, lo);
            d_Ahi[w][head][t][64 + c] = hi;
            d_Alo[w][head][t][64 + c] = lo;
        }
    }
    for (int idx = tid; idx < 64 * 6; idx += 256) {
        int tl = idx >> 6, c = idx & 63;
        int t = t0 + tl;
        if (t < LTT) {
            float v = (c == 63) ? (t * (1.0f / 93.0f)) : xs[tl + 2][c];
            __nv_bfloat16 hi, lo;
            split_bf16(v, hi, lo);
            d_Ahi[w][head][t][c] = hi;
            d_Alo[w][head][t][c] = lo;
        }
    }
    if (blockIdx.y == 15) {
        for (int idx = tid; idx < 2 * CCH; idx += 256) {
            int t = 94 + idx / CCH, c = idx % CCH;
            d_Ahi[w][head][t][c] = __float2bfloat16(0.0f);
            d_Alo[w][head][t][c] = __float2bfloat16(0.0f);
        }
    }
}

// ---------------------------------------------------------------------------
// Kernel 2: raw-mma bf16-split, register epilogue + atomic accumulation
// grid (256, 2), 256 threads, ~201 KB dynamic smem, 1 CTA/SM
// ---------------------------------------------------------------------------
#define WS2 200   // bf16 row stride (400 B)
#define AFS 100   // fp32 row stride for A half-tile

#define OFF_WHI  0
#define OFF_WLO  38400
#define OFF_AHI  76800
#define OFF_ALO  115200
#define OFF_AF   153600   // [96][100] fp32 (current half)
#define OFF_W1   192000
#define OFF_ACC  192768   // [4 heads][4][96] (0=alpha 1=delta 2=beta 3=gamma)
#define OFF_E    198912   // [4 heads][96]
#define OFF_PREF 200448
#define SM_TOT   200832

__global__ __launch_bounds__(256, 1) void k_proj(
    const float* __restrict__ Wlq, const float* __restrict__ blq,
    const float* __restrict__ Wlk, const float* __restrict__ blk)
{
    extern __shared__ char sm[];
    __nv_bfloat16* Whi = (__nv_bfloat16*)(sm + OFF_WHI);
    __nv_bfloat16* Wlo = (__nv_bfloat16*)(sm + OFF_WLO);
    __nv_bfloat16* Ahi = (__nv_bfloat16*)(sm + OFF_AHI);
    __nv_bfloat16* Alo = (__nv_bfloat16*)(sm + OFF_ALO);
    float* AF    = (float*)(sm + OFF_AF);
    float* w1sh  = (float*)(sm + OFF_W1);
    float* accS  = (float*)(sm + OFF_ACC);
    float* Esh   = (float*)(sm + OFF_E);
    float* prefS = (float*)(sm + OFF_PREF);

    int o = blockIdx.x, w = blockIdx.y;
    const float* Wl = w ? Wlk : Wlq;
    const float* bl = w ? blk : blq;
    int tid = threadIdx.x, lane = tid & 31, warp = tid >> 5;
    int wm = warp >> 2, wn = warp & 3;   // 2 x 4 warp grid over D 96x96

    uint32_t aHiB = smem_u32(Ahi), aLoB = smem_u32(Alo);
    uint32_t wHiB = smem_u32(Whi), wLoB = smem_u32(Wlo);

    // zero accumulators, load w1
    for (int g = tid; g < 4 * 4 * 96 + 4 * 96; g += 256) accS[g] = 0.0f;
    for (int g = tid; g < CCH; g += 256) w1sh[g] = Wl[(size_t)o * SIGD + g];
    float blo = bl[o];

    for (int half = 0; half < 2; half++) {
        // ---- W2 half -> bf16 hi/lo (vectorized) ----
        __syncthreads();
        const float4* Wsrc = (const float4*)(Wl + (size_t)o * SIGD + CCH + (size_t)half * 96 * CCH);
        for (int g = tid; g < 4608; g += 256) {
            float4 vv = Wsrc[g];
            int e0 = g * 4;
            int i = e0 / CCH, j = e0 - i * CCH;
            __nv_bfloat16 h0, l0, h1, l1, h2, l2, h3, l3;
            split_bf16(vv.x, h0, l0); split_bf16(vv.y, h1, l1);
            split_bf16(vv.z, h2, l2); split_bf16(vv.w, h3, l3);
            __nv_bfloat162 hp0, hp1, lp0, lp1;
            hp0.x = h0; hp0.y = h1; hp1.x = h2; hp1.y = h3;
            lp0.x = l0; lp0.y = l1; lp1.x = l2; lp1.y = l3;
            uint2 hu, lu;
            hu.x = *(uint32_t*)&hp0; hu.y = *(uint32_t*)&hp1;
            lu.x = *(uint32_t*)&lp0; lu.y = *(uint32_t*)&lp1;
            *(uint2*)&Whi[i * WS2 + j] = hu;
            *(uint2*)&Wlo[i * WS2 + j] = lu;
        }
        __syncthreads();

        for (int head = 0; head < 4; head++) {
            // ---- A hi/lo copy (uint4) + AF fp32 half-tile from global ----
            const uint4* srcH = (const uint4*)&d_Ahi[w][head][0][0];
            const uint4* srcL = (const uint4*)&d_Alo[w][head][0][0];
            for (int g = tid; g < 96 * CCH / 8; g += 256) {
                int row = g / 24, c8 = g - row * 24;
                *(uint4*)&Ahi[row * WS2 + c8 * 8] = srcH[g];
                *(uint4*)&Alo[row * WS2 + c8 * 8] = srcL[g];
            }
            const uint32_t* gH = (const uint32_t*)&d_Ahi[w][head][0][0];
            const uint32_t* gL = (const uint32_t*)&d_Alo[w][head][0][0];
            for (int g = tid; g < 96 * 48; g += 256) {
                int row = g / 48, wd = g - row * 48;
                uint32_t hw = gH[row * 96 + half * 48 + wd];
                uint32_t lw = gL[row * 96 + half * 48 + wd];
                __nv_bfloat162 hh = *(__nv_bfloat162*)&hw;
                __nv_bfloat162 ll = *(__nv_bfloat162*)&lw;
                float2 f;
                f.x = __bfloat162float(hh.x) + __bfloat162float(ll.x);
                f.y = __bfloat162float(hh.y) + __bfloat162float(ll.y);
                *(float2*)&AF[row * AFS + 2 * wd] = f;
            }
            __syncthreads();

            // ---- raw mma: D = A @ Whalf^T in registers ----
            float acc[3][3][4];
            #pragma unroll
            for (int mt = 0; mt < 3; mt++)
                #pragma unroll
                for (int nt = 0; nt < 3; nt++)
                    #pragma unroll
                    for (int e = 0; e < 4; e++) acc[mt][nt][e] = 0.0f;

            {
                uint32_t aRow = 48 * wm + (lane & 15);
                uint32_t aColHalf = (lane >> 4) * 16;
                uint32_t bRow = 24 * wn + (lane & 7);
                uint32_t bColHalf = ((lane >> 3) & 1) * 16;

                #pragma unroll
                for (int k = 0; k < 12; k++) {
                    uint32_t kb = k * 32;
                    uint32_t ah[3][4], al[3][4], bh[3][2], blr[3][2];
                    #pragma unroll
                    for (int mt = 0; mt < 3; mt++) {
                        uint32_t off = (aRow + 16u * mt) * 400u + kb + aColHalf;
                        ldsm_x4(ah[mt], aHiB + off);
                        ldsm_x4(al[mt], aLoB + off);
                    }
                    #pragma unroll
                    for (int nt = 0; nt < 3; nt++) {
                        uint32_t off = (bRow + 8u * nt) * 400u + kb + bColHalf;
                        ldsm_x2(bh[nt],  wHiB + off);
                        ldsm_x2(blr[nt], wLoB + off);
                    }
                    #pragma unroll
                    for (int mt = 0; mt < 3; mt++)
                        #pragma unroll
                        for (int nt = 0; nt < 3; nt++) {
                            mma16816(acc[mt][nt], ah[mt], bh[nt]);
                            mma16816(acc[mt][nt], ah[mt], blr[nt]);
                            mma16816(acc[mt][nt], al[mt], bh[nt]);
                        }
                }
            }

            // ---- register epilogue: tridiagonal partials + atomic accum ----
            {
                int r0 = 48 * wm + (lane >> 2);
                int cA = 2 * (lane & 3);
                float* accH = accS + head * 384;
                #pragma unroll
                for (int mt = 0; mt < 3; mt++) {
                    #pragma unroll
                    for (int hr = 0; hr < 2; hr++) {
                        int t = r0 + 16 * mt + 8 * hr;
                        int tm1 = (t >= 1) ? t - 1 : 0;
                        int tp1 = (t < 95) ? t + 1 : 95;
                        float pa = 0, pd = 0, pb = 0, pg = 0;
                        #pragma unroll
                        for (int nt = 0; nt < 3; nt++) {
                            int c = 24 * wn + 8 * nt + cA;
                            float z0 = acc[mt][nt][2 * hr + 0];
                            float z1 = acc[mt][nt][2 * hr + 1];
                            float2 at = *(float2*)&AF[t   * AFS + c];
                            float2 a0 = *(float2*)&AF[c];
                            float2 am = *(float2*)&AF[tm1 * AFS + c];
                            float2 ap = *(float2*)&AF[tp1 * AFS + c];
                            pa += z0 * at.x + z1 * at.y;
                            pd += z0 * a0.x + z1 * a0.y;
                            pb += z0 * am.x + z1 * am.y;
                            pg += z0 * ap.x + z1 * ap.y;
                        }
                        #pragma unroll
                        for (int off = 1; off <= 2; off <<= 1) {
                            pa += __shfl_xor_sync(0xffffffffu, pa, off);
                            pd += __shfl_xor_sync(0xffffffffu, pd, off);
                            pb += __shfl_xor_sync(0xffffffffu, pb, off);
                            pg += __shfl_xor_sync(0xffffffffu, pg, off);
                        }
                        if ((lane & 3) == 0 && t < LTT) {
                            atomicAdd(&accH[0 * 96 + t], pa);
                            atomicAdd(&accH[1 * 96 + t], pd);
                            if (t >= 1)  atomicAdd(&accH[2 * 96 + t - 1], pb);
                            if (t <= 92) atomicAdd(&accH[3 * 96 + t], pg);
                        }
                    }
                }
            }

            // ---- e_t (once per head, on half 0) ----
            if (half == 0 && tid < 192) {
                int t = tid >> 1, seg = tid & 1;
                float pe = 0.0f;
                #pragma unroll 8
                for (int wd = 0; wd < 48; wd++) {
                    int c = seg * 96 + 2 * wd;
                    __nv_bfloat162 hh = *(__nv_bfloat162*)&Ahi[t * WS2 + c];
                    __nv_bfloat162 ll = *(__nv_bfloat162*)&Alo[t * WS2 + c];
                    float2 w1v = *(float2*)&w1sh[c];
                    pe += w1v.x * (__bfloat162float(hh.x) + __bfloat162float(ll.x))
                        + w1v.y * (__bfloat162float(hh.y) + __bfloat162float(ll.y));
                }
                pe += __shfl_xor_sync(0xffffffffu, pe, 1);
                if (seg == 0 && t < LTT) Esh[head * 96 + t] = pe;
            }
            __syncthreads();
        }
    }

    // ---- per-head scan + P assembly ----
    for (int head = 0; head < 4; head++) {
        float* accH = accS + head * 384;
        float* eH = Esh + head * 96;
        if (warp == 0) {
            float carry = 0.0f;
            for (int ch = 0; ch < 3; ch++) {
                int idx = ch * 32 + lane;
                float vv = (idx < NTT) ? (accH[2 * 96 + idx] - accH[3 * 96 + idx]) : 0.0f;
                #pragma unroll
                for (int off = 1; off < 32; off <<= 1) {
                    float n = __shfl_up_sync(0xffffffffu, vv, off);
                    if (lane >= off) vv += n;
                }
                vv += carry;
                if (idx < NTT) prefS[idx] = vv;
                carry = __shfl_sync(0xffffffffu, vv, 31);
            }
        }
        __syncthreads();
        if (tid < NTT) {
            int t = tid;
            float Pv = blo + eH[t + 1] - eH[0]
                     + 0.5f * (accH[0 * 96 + t + 1] + accH[0 * 96 + 0])
                     - accH[1 * 96 + t + 1]
                     + 0.5f * prefS[t];
            d_P[w][head][t][o] = Pv;
        }
        __syncthreads();
    }
}

// ---------------------------------------------------------------------------
// Kernel 3: attn = tanh(Pq @ Pk^T) on 93x93 core; out = attn @ v_agg
// ---------------------------------------------------------------------------
#define TS 260

__global__ __launch_bounds__(256) void k_attn(
    const float* __restrict__ v, float* __restrict__ out)
{
    extern __shared__ float sm3[];
    float* Tq = sm3;
    float* Tk = Tq + NTT * TS;
    float* vg = Tk + NTT * TS;
    float* Gr = vg + NTT * EVD;

    int bh = blockIdx.x, zh = blockIdx.y;
    int tid = threadIdx.x, lane = tid & 31, warp = tid >> 5;

    for (int g = tid; g < NTT * OO; g += 256) {
        int t = g >> 8, o = g & 255;
        Tq[t * TS + o] = d_P[0][bh][t][o];
        Tk[t * TS + o] = d_P[1][bh][t][o];
    }
    for (int g = tid; g < NTT * EVD; g += 256) {
        int t = g >> 6, e = g & 63;
        float s = v[((size_t)bh * NNN + 2 * t) * EVD + e]
                + v[((size_t)bh * NNN + 2 * t + 1) * EVD + e];
        if (t == 92) s += v[((size_t)bh * NNN + 186) * EVD + e];
        vg[g] = s;
    }
    __syncthreads();

    int x0 = zh * 24;
    for (int xx = 0; xx < 3; xx++) {
        int x = x0 + warp + 8 * xx;
        if (x < NTT) {
            int ty0 = lane, ty1 = lane + 32, ty2 = lane + 64;
            int ty2c = (ty2 < NTT) ? ty2 : 0;
            const float4* tq = (const float4*)(Tq + x * TS);
            const float4* k0 = (const float4*)(Tk + ty0 * TS);
            const float4* k1 = (const float4*)(Tk + ty1 * TS);
            const float4* k2 = (const float4*)(Tk + ty2c * TS);
            float a0 = 0, a1 = 0, a2 = 0;
            #pragma unroll 8
            for (int o4 = 0; o4 < OO / 4; o4++) {
                float4 qv = tq[o4];
                float4 b0 = k0[o4];
                a0 += qv.x * b0.x + qv.y * b0.y + qv.z * b0.z + qv.w * b0.w;
                float4 b1 = k1[o4];
                a1 += qv.x * b1.x + qv.y * b1.y + qv.z * b1.z + qv.w * b1.w;
                float4 b2 = k2[o4];
                a2 += qv.x * b2.x + qv.y * b2.y + qv.z * b2.z + qv.w * b2.w;
            }
            __syncwarp();
            Gr[warp * 96 + ty0] = tanhf(a0);
            Gr[warp * 96 + ty1] = tanhf(a1);
            if (ty2 < NTT) Gr[warp * 96 + ty2] = tanhf(a2);
            __syncwarp();
            float o0 = 0, o1 = 0;
            for (int ty = 0; ty < NTT; ty++) {
                float g = Gr[warp * 96 + ty];
                o0 += g * vg[ty * EVD + lane];
                o1 += g * vg[ty * EVD + lane + 32];
            }
            size_t base = ((size_t)bh * NNN + 2 * x) * EVD;
            out[base + lane]            = o0;
            out[base + lane + 32]       = o1;
            out[base + EVD + lane]      = o0;
            out[base + EVD + lane + 32] = o1;
            if (x == 92) {
                size_t bl2 = ((size_t)bh * NNN + 186) * EVD;
                out[bl2 + lane]      = o0;
                out[bl2 + lane + 32] = o1;
            }
        }
    }
}

// ---------------------------------------------------------------------------
extern "C" void kernel_launch(void* const* d_in, const int* in_sizes, int n_in,
                              void* d_out, int out_size)
{
    const float* q   = (const float*)d_in[0];
    const float* k   = (const float*)d_in[1];
    const float* v   = (const float*)d_in[2];
    const float* Wq1 = (const float*)d_in[3];
    const float* bq1 = (const float*)d_in[4];
    const float* Wq2 = (const float*)d_in[5];
    const float* bq2 = (const float*)d_in[6];
    const float* Wk1 = (const float*)d_in[7];
    const float* bk1 = (const float*)d_in[8];
    const float* Wk2 = (const float*)d_in[9];
    const float* bk2 = (const float*)d_in[10];
    const float* Wlq = (const float*)d_in[11];
    const float* blq = (const float*)d_in[12];
    const float* Wlk = (const float*)d_in[13];
    const float* blk = (const float*)d_in[14];
    float* out = (float*)d_out;

    const int SM3 = (2 * NTT * TS + NTT * EVD + 8 * 96) * 4;
    static int attr_done = 0;
    if (!attr_done) {
        cudaFuncSetAttribute(k_augment, cudaFuncAttributeMaxDynamicSharedMemorySize, AUG_SMEM);
        cudaFuncSetAttribute(k_proj, cudaFuncAttributeMaxDynamicSharedMemorySize, SM_TOT);
        cudaFuncSetAttribute(k_attn, cudaFuncAttributeMaxDynamicSharedMemorySize, SM3);
        attr_done = 1;
    }

    k_augment<<<dim3(8, 16), 256, AUG_SMEM>>>(q, k, Wq1, bq1, Wq2, bq2, Wk1, bk1, Wk2, bk2);
    k_proj<<<dim3(256, 2), 256, SM_TOT>>>(Wlq, blq, Wlk, blk);
    k_attn<<<dim3(4, 4), 256, SM3>>>(v, out);
}

// round 9
// speedup vs baseline: 2.2390x; 1.0642x over previous
#include <cuda_runtime.h>
#include <cuda_bf16.h>
#include <cstdint>
#include <math.h>

#define CCH  192
#define LTT  94
#define NTT  93
#define NNN  187
#define OO   256
#define SIGD 37056
#define EVD  64

// A as bf16 hi/lo split, rows 94,95 zero. [w][head][96][192]
__device__ __nv_bfloat16 d_Ahi[2][4][96][CCH];
__device__ __nv_bfloat16 d_Alo[2][4][96][CCH];
__device__ float d_P[2][4][NTT][OO];      // projected signatures

__device__ __forceinline__ void split_bf16(float v, __nv_bfloat16& hi, __nv_bfloat16& lo) {
    hi = __float2bfloat16(v);
    lo = __float2bfloat16(v - __bfloat162float(hi));
}
__device__ __forceinline__ uint32_t smem_u32(const void* p) {
    uint32_t a;
    asm("{ .reg .u64 t; cvta.to.shared.u64 t, %1; cvt.u32.u64 %0, t; }" : "=r"(a) : "l"(p));
    return a;
}
__device__ __forceinline__ void ldsm_x4(uint32_t* r, uint32_t addr) {
    asm volatile("ldmatrix.sync.aligned.m8n8.x4.shared.b16 {%0,%1,%2,%3}, [%4];"
        : "=r"(r[0]), "=r"(r[1]), "=r"(r[2]), "=r"(r[3]) : "r"(addr));
}
__device__ __forceinline__ void ldsm_x2(uint32_t* r, uint32_t addr) {
    asm volatile("ldmatrix.sync.aligned.m8n8.x2.shared.b16 {%0,%1}, [%2];"
        : "=r"(r[0]), "=r"(r[1]) : "r"(addr));
}
__device__ __forceinline__ void mma16816(float* c, const uint32_t* a, const uint32_t* b) {
    asm volatile("mma.sync.aligned.m16n8k16.row.col.f32.bf16.bf16.f32 "
        "{%0,%1,%2,%3}, {%4,%5,%6,%7}, {%8,%9}, {%0,%1,%2,%3};"
        : "+f"(c[0]), "+f"(c[1]), "+f"(c[2]), "+f"(c[3])
        : "r"(a[0]), "r"(a[1]), "r"(a[2]), "r"(a[3]), "r"(b[0]), "r"(b[1]));
}
__device__ __forceinline__ float2 bf2pair(const __nv_bfloat16* hiP, const __nv_bfloat16* loP) {
    __nv_bfloat162 h = *(const __nv_bfloat162*)hiP;
    __nv_bfloat162 l = *(const __nv_bfloat162*)loP;
    float2 f;
    f.x = __bfloat162float(h.x) + __bfloat162float(l.x);
    f.y = __bfloat162float(h.y) + __bfloat162float(l.y);
    return f;
}

// ---------------------------------------------------------------------------
// Kernel 1: augmentation -> d_Ahi/d_Alo   grid (8, 16), 256 thr
// ---------------------------------------------------------------------------
#define AUG_SMEM (12096 * 4 + 128 * 65 * 4)

__global__ __launch_bounds__(256) void k_augment(
    const float* __restrict__ qg, const float* __restrict__ kg,
    const float* __restrict__ Wq1, const float* __restrict__ bq1,
    const float* __restrict__ Wq2, const float* __restrict__ bq2,
    const float* __restrict__ Wk1, const float* __restrict__ bk1,
    const float* __restrict__ Wk2, const float* __restrict__ bk2)
{
    extern __shared__ float dyn[];
    float* W1s = dyn;
    float* W2s = dyn + 12096;
    __shared__ float xs[8][65];
    __shared__ float y1s[64][6];

    int wh = blockIdx.x;
    int w = wh >> 2, head = wh & 3;
    int b = head >> 1, h = head & 1;
    int t0 = blockIdx.y * 6;
    const float* x  = w ? kg  : qg;
    const float* W1 = w ? Wk1 : Wq1;
    const float* B1 = w ? bk1 : bq1;
    const float* W2 = w ? Wk2 : Wq2;
    const float* B2 = w ? bk2 : bq2;
    int tid = threadIdx.x;

    const float4* W1v = (const float4*)W1;
    for (int g = tid; g < 3024; g += 256) ((float4*)W1s)[g] = W1v[g];
    const float4* W2v = (const float4*)W2;
    for (int g = tid; g < 2048; g += 256) {
        float4 vv = W2v[g];
        int c = (g * 4) >> 6, j = (g * 4) & 63;
        float* dst = W2s + c * 65 + j;
        dst[0] = vv.x; dst[1] = vv.y; dst[2] = vv.z; dst[3] = vv.w;
    }
    for (int idx = tid; idx < 8 * 63; idx += 256) {
        int r = idx / 63, e = idx - r * 63;
        int l = t0 + r;
        if (l < 96) xs[r][e] = x[((b * 96 + l) * 2 + h) * 63 + e];
    }
    __syncthreads();

    for (int idx = tid; idx < 64 * 6; idx += 256) {
        int c = idx / 6, tl = idx - c * 6;
        int t = t0 + tl;
        float acc = 0.0f;
        if (t < LTT) {
            const float* wr = W1s + c * 189;
            float a0 = 0, a1 = 0, a2 = 0;
            #pragma unroll 9
            for (int e = 0; e < 63; e++) {
                a0 += wr[e * 3 + 0] * xs[tl][e];
                a1 += wr[e * 3 + 1] * xs[tl + 1][e];
                a2 += wr[e * 3 + 2] * xs[tl + 2][e];
            }
            acc = B1[c] + a0 + a1 + a2;
        }
        y1s[c][tl] = acc;
    }
    __syncthreads();

    for (int idx = tid; idx < 128 * 6; idx += 256) {
        int c = idx / 6, tl = idx - c * 6;
        int t = t0 + tl;
        if (t < LTT) {
            const float* wr = W2s + c * 65;
            float a0 = 0, a1 = 0;
            #pragma unroll
            for (int j = 0; j < 64; j += 2) {
                a0 += wr[j]     * y1s[j][tl];
                a1 += wr[j + 1] * y1s[j + 1][tl];
            }
            float v = fmaxf(B2[c] + a0 + a1, 0.0f);
            __nv_bfloat16 hi, lo;
            split_bf16(v, hi, lo);
            d_Ahi[w][head][t][64 + c] = hi;
            d_Alo[w][head][t][64 + c] = lo;
        }
    }
    for (int idx = tid; idx < 64 * 6; idx += 256) {
        int tl = idx >> 6, c = idx & 63;
        int t = t0 + tl;
        if (t < LTT) {
            float v = (c == 63) ? (t * (1.0f / 93.0f)) : xs[tl + 2][c];
            __nv_bfloat16 hi, lo;
            split_bf16(v, hi, lo);
            d_Ahi[w][head][t][c] = hi;
            d_Alo[w][head][t][c] = lo;
        }
    }
    if (blockIdx.y == 15) {
        for (int idx = tid; idx < 2 * CCH; idx += 256) {
            int t = 94 + idx / CCH, c = idx % CCH;
            d_Ahi[w][head][t][c] = __float2bfloat16(0.0f);
            d_Alo[w][head][t][c] = __float2bfloat16(0.0f);
        }
    }
}

// ---------------------------------------------------------------------------
// Kernel 2: chunked-W raw-mma, register-accumulated dots, 2 CTAs/SM
// grid (256, 2), 256 threads, 111,232 B dynamic smem
// ---------------------------------------------------------------------------
#define WS2 200   // bf16 row stride (400 B)

#define OFF_AHI  0
#define OFF_ALO  38400
#define OFF_WHI  76800
#define OFF_WLO  89600
#define OFF_ACC  102400   // [4 heads][4][96] (0=alpha 1=delta 2=beta 3=gamma)
#define OFF_E    108544   // [4 heads][96]
#define OFF_W1   110080   // [192]
#define OFF_PREF 110848   // [96]
#define SM_TOT   111232

__global__ __launch_bounds__(256, 2) void k_proj(
    const float* __restrict__ Wlq, const float* __restrict__ blq,
    const float* __restrict__ Wlk, const float* __restrict__ blk)
{
    extern __shared__ char sm[];
    __nv_bfloat16* Ahi = (__nv_bfloat16*)(sm + OFF_AHI);
    __nv_bfloat16* Alo = (__nv_bfloat16*)(sm + OFF_ALO);
    __nv_bfloat16* Whi = (__nv_bfloat16*)(sm + OFF_WHI);
    __nv_bfloat16* Wlo = (__nv_bfloat16*)(sm + OFF_WLO);
    float* accS  = (float*)(sm + OFF_ACC);
    float* Esh   = (float*)(sm + OFF_E);
    float* w1sh  = (float*)(sm + OFF_W1);
    float* prefS = (float*)(sm + OFF_PREF);

    int o = blockIdx.x, w = blockIdx.y;
    const float* Wl = w ? Wlk : Wlq;
    const float* bl = w ? blk : blq;
    int tid = threadIdx.x, lane = tid & 31, warp = tid >> 5;
    int wm = warp >> 2, wn = warp & 3;   // 2 x 4 warp grid (M=48/warp, N=8/warp)

    uint32_t aHiB = smem_u32(Ahi), aLoB = smem_u32(Alo);
    uint32_t wHiB = smem_u32(Whi), wLoB = smem_u32(Wlo);

    for (int g = tid; g < 4 * 4 * 96; g += 256) accS[g] = 0.0f;
    for (int g = tid; g < CCH; g += 256) w1sh[g] = Wl[(size_t)o * SIGD + g];
    float blo = bl[o];

    const float* Wbase = Wl + (size_t)o * SIGD + CCH;

    uint32_t aRow = 48 * wm + (lane & 15);
    uint32_t aColHalf = (lane >> 4) * 16;
    uint32_t bRow = 8 * wn + (lane & 7);
    uint32_t bColHalf = ((lane >> 3) & 1) * 16;
    int r0 = 48 * wm + (lane >> 2);
    int iw0 = 4 * wn + (lane & 3);

    for (int head = 0; head < 4; head++) {
        __syncthreads();   // protect A / W / Esh from previous iteration readers

        // ---- A hi/lo -> smem (uint4) ----
        const uint4* srcH = (const uint4*)&d_Ahi[w][head][0][0];
        const uint4* srcL = (const uint4*)&d_Alo[w][head][0][0];
        for (int g = tid; g < 2304; g += 256) {
            int row = g / 24, c8 = g - row * 24;
            *(uint4*)&Ahi[row * WS2 + c8 * 8] = srcH[g];
            *(uint4*)&Alo[row * WS2 + c8 * 8] = srcL[g];
        }
        __syncthreads();

        // dot partial registers, accumulated across all 6 W-chunks
        float dpa[3][2], dpd[3][2], dpb[3][2], dpg[3][2];
        #pragma unroll
        for (int mt = 0; mt < 3; mt++)
            #pragma unroll
            for (int hr = 0; hr < 2; hr++) {
                dpa[mt][hr] = 0; dpd[mt][hr] = 0; dpb[mt][hr] = 0; dpg[mt][hr] = 0;
            }

        for (int chunk = 0; chunk < 6; chunk++) {
            // ---- convert W chunk (32 rows x 192) -> bf16 hi/lo ----
            const float4* Wc = (const float4*)(Wbase + (size_t)chunk * 32 * CCH);
            for (int g = tid; g < 1536; g += 256) {
                float4 vv = Wc[g];
                int e0 = g * 4;
                int i = e0 / CCH, j = e0 - i * CCH;
                __nv_bfloat16 h0, l0, h1, l1, h2, l2, h3, l3;
                split_bf16(vv.x, h0, l0); split_bf16(vv.y, h1, l1);
                split_bf16(vv.z, h2, l2); split_bf16(vv.w, h3, l3);
                __nv_bfloat162 hp0, hp1, lp0, lp1;
                hp0.x = h0; hp0.y = h1; hp1.x = h2; hp1.y = h3;
                lp0.x = l0; lp0.y = l1; lp1.x = l2; lp1.y = l3;
                uint2 hu, lu;
                hu.x = *(uint32_t*)&hp0; hu.y = *(uint32_t*)&hp1;
                lu.x = *(uint32_t*)&lp0; lu.y = *(uint32_t*)&lp1;
                *(uint2*)&Whi[i * WS2 + j] = hu;
                *(uint2*)&Wlo[i * WS2 + j] = lu;
            }
            __syncthreads();

            // ---- mma: D-chunk (96 x 32), this warp: 48 x 8 ----
            float acc[3][4];
            #pragma unroll
            for (int mt = 0; mt < 3; mt++)
                #pragma unroll
                for (int e = 0; e < 4; e++) acc[mt][e] = 0.0f;

            #pragma unroll
            for (int k = 0; k < 12; k++) {
                uint32_t kb = k * 32;
                uint32_t ah[3][4], al[3][4], bh[2], blr[2];
                #pragma unroll
                for (int mt = 0; mt < 3; mt++) {
                    uint32_t off = (aRow + 16u * mt) * 400u + kb + aColHalf;
                    ldsm_x4(ah[mt], aHiB + off);
                    ldsm_x4(al[mt], aLoB + off);
                }
                {
                    uint32_t off = bRow * 400u + kb + bColHalf;
                    ldsm_x2(bh,  wHiB + off);
                    ldsm_x2(blr, wLoB + off);
                }
                #pragma unroll
                for (int mt = 0; mt < 3; mt++) {
                    mma16816(acc[mt], ah[mt], bh);
                    mma16816(acc[mt], ah[mt], blr);
                    mma16816(acc[mt], al[mt], bh);
                }
            }

            // ---- epilogue partials vs A columns i = chunk*32 + wn*8 + 2*(lane&3) ----
            int iw = chunk * 16 + iw0;   // bf16x2 word index into A row
            #pragma unroll
            for (int mt = 0; mt < 3; mt++) {
                #pragma unroll
                for (int hr = 0; hr < 2; hr++) {
                    int t = r0 + 16 * mt + 8 * hr;
                    int tm1 = (t >= 1) ? t - 1 : 0;
                    int tp1 = (t < 95) ? t + 1 : 95;
                    float z0 = acc[mt][2 * hr + 0];
                    float z1 = acc[mt][2 * hr + 1];
                    float2 at = bf2pair(&Ahi[t   * WS2 + 2 * iw], &Alo[t   * WS2 + 2 * iw]);
                    float2 a0 = bf2pair(&Ahi[2 * iw],             &Alo[2 * iw]);
                    float2 am = bf2pair(&Ahi[tm1 * WS2 + 2 * iw], &Alo[tm1 * WS2 + 2 * iw]);
                    float2 ap = bf2pair(&Ahi[tp1 * WS2 + 2 * iw], &Alo[tp1 * WS2 + 2 * iw]);
                    dpa[mt][hr] += z0 * at.x + z1 * at.y;
                    dpd[mt][hr] += z0 * a0.x + z1 * a0.y;
                    dpb[mt][hr] += z0 * am.x + z1 * am.y;
                    dpg[mt][hr] += z0 * ap.x + z1 * ap.y;
                }
            }
            __syncthreads();   // before overwriting W chunk
        }

        // ---- reduce over lane&3 group, atomic into per-head accumulators ----
        float* accH = accS + head * 384;
        #pragma unroll
        for (int mt = 0; mt < 3; mt++) {
            #pragma unroll
            for (int hr = 0; hr < 2; hr++) {
                int t = r0 + 16 * mt + 8 * hr;
                float pa = dpa[mt][hr], pd = dpd[mt][hr];
                float pb = dpb[mt][hr], pg = dpg[mt][hr];
                #pragma unroll
                for (int off = 1; off <= 2; off <<= 1) {
                    pa += __shfl_xor_sync(0xffffffffu, pa, off);
                    pd += __shfl_xor_sync(0xffffffffu, pd, off);
                    pb += __shfl_xor_sync(0xffffffffu, pb, off);
                    pg += __shfl_xor_sync(0xffffffffu, pg, off);
                }
                if ((lane & 3) == 0 && t < LTT) {
                    atomicAdd(&accH[0 * 96 + t], pa);
                    atomicAdd(&accH[1 * 96 + t], pd);
                    if (t >= 1)  atomicAdd(&accH[2 * 96 + t - 1], pb);
                    if (t <= 92) atomicAdd(&accH[3 * 96 + t], pg);
                }
            }
        }

        // ---- e_t for this head (WHOLE warps 0..5; store guarded) ----
        if (tid < 192) {
            int t = tid >> 1, seg = tid & 1;   // t in 0..95; rows 94,95 are zero
            float pe = 0.0f;
            #pragma unroll 8
            for (int wd = 0; wd < 48; wd++) {
                int c = seg * 96 + 2 * wd;
                float2 av = bf2pair(&Ahi[t * WS2 + c], &Alo[t * WS2 + c]);
                float2 w1v = *(float2*)&w1sh[c];
                pe += w1v.x * av.x + w1v.y * av.y;
            }
            pe += __shfl_xor_sync(0xffffffffu, pe, 1);
            if (seg == 0 && t < LTT) Esh[head * 96 + t] = pe;
        }
    }
    __syncthreads();

    // ---- per-head scan + P assembly ----
    for (int head = 0; head < 4; head++) {
        float* accH = accS + head * 384;
        float* eH = Esh + head * 96;
        if (warp == 0) {
            float carry = 0.0f;
            for (int ch = 0; ch < 3; ch++) {
                int idx = ch * 32 + lane;
                float vv = (idx < NTT) ? (accH[2 * 96 + idx] - accH[3 * 96 + idx]) : 0.0f;
                #pragma unroll
                for (int off = 1; off < 32; off <<= 1) {
                    float n = __shfl_up_sync(0xffffffffu, vv, off);
                    if (lane >= off) vv += n;
                }
                vv += carry;
                if (idx < NTT) prefS[idx] = vv;
                carry = __shfl_sync(0xffffffffu, vv, 31);
            }
        }
        __syncthreads();
        if (tid < NTT) {
            int t = tid;
            float Pv = blo + eH[t + 1] - eH[0]
                     + 0.5f * (accH[0 * 96 + t + 1] + accH[0 * 96 + 0])
                     - accH[1 * 96 + t + 1]
                     + 0.5f * prefS[t];
            d_P[w][head][t][o] = Pv;
        }
        __syncthreads();
    }
}

// ---------------------------------------------------------------------------
// Kernel 3: attn = tanh(Pq @ Pk^T) on 93x93 core; out = attn @ v_agg
// ---------------------------------------------------------------------------
#define TS 260

__global__ __launch_bounds__(256) void k_attn(
    const float* __restrict__ v, float* __restrict__ out)
{
    extern __shared__ float sm3[];
    float* Tq = sm3;
    float* Tk = Tq + NTT * TS;
    float* vg = Tk + NTT * TS;
    float* Gr = vg + NTT * EVD;

    int bh = blockIdx.x, zh = blockIdx.y;
    int tid = threadIdx.x, lane = tid & 31, warp = tid >> 5;

    for (int g = tid; g < NTT * OO; g += 256) {
        int t = g >> 8, o = g & 255;
        Tq[t * TS + o] = d_P[0][bh][t][o];
        Tk[t * TS + o] = d_P[1][bh][t][o];
    }
    for (int g = tid; g < NTT * EVD; g += 256) {
        int t = g >> 6, e = g & 63;
        float s = v[((size_t)bh * NNN + 2 * t) * EVD + e]
                + v[((size_t)bh * NNN + 2 * t + 1) * EVD + e];
        if (t == 92) s += v[((size_t)bh * NNN + 186) * EVD + e];
        vg[g] = s;
    }
    __syncthreads();

    int x0 = zh * 24;
    for (int xx = 0; xx < 3; xx++) {
        int x = x0 + warp + 8 * xx;
        if (x < NTT) {
            int ty0 = lane, ty1 = lane + 32, ty2 = lane + 64;
            int ty2c = (ty2 < NTT) ? ty2 : 0;
            const float4* tq = (const float4*)(Tq + x * TS);
            const float4* k0 = (const float4*)(Tk + ty0 * TS);
            const float4* k1 = (const float4*)(Tk + ty1 * TS);
            const float4* k2 = (const float4*)(Tk + ty2c * TS);
            float a0 = 0, a1 = 0, a2 = 0;
            #pragma unroll 8
            for (int o4 = 0; o4 < OO / 4; o4++) {
                float4 qv = tq[o4];
                float4 b0 = k0[o4];
                a0 += qv.x * b0.x + qv.y * b0.y + qv.z * b0.z + qv.w * b0.w;
                float4 b1 = k1[o4];
                a1 += qv.x * b1.x + qv.y * b1.y + qv.z * b1.z + qv.w * b1.w;
                float4 b2 = k2[o4];
                a2 += qv.x * b2.x + qv.y * b2.y + qv.z * b2.z + qv.w * b2.w;
            }
            __syncwarp();
            Gr[warp * 96 + ty0] = tanhf(a0);
            Gr[warp * 96 + ty1] = tanhf(a1);
            if (ty2 < NTT) Gr[warp * 96 + ty2] = tanhf(a2);
            __syncwarp();
            float o0 = 0, o1 = 0;
            for (int ty = 0; ty < NTT; ty++) {
                float g = Gr[warp * 96 + ty];
                o0 += g * vg[ty * EVD + lane];
                o1 += g * vg[ty * EVD + lane + 32];
            }
            size_t base = ((size_t)bh * NNN + 2 * x) * EVD;
            out[base + lane]            = o0;
            out[base + lane + 32]       = o1;
            out[base + EVD + lane]      = o0;
            out[base + EVD + lane + 32] = o1;
            if (x == 92) {
                size_t bl2 = ((size_t)bh * NNN + 186) * EVD;
                out[bl2 + lane]      = o0;
                out[bl2 + lane + 32] = o1;
            }
        }
    }
}

// ---------------------------------------------------------------------------
extern "C" void kernel_launch(void* const* d_in, const int* in_sizes, int n_in,
                              void* d_out, int out_size)
{
    const float* q   = (const float*)d_in[0];
    const float* k   = (const float*)d_in[1];
    const float* v   = (const float*)d_in[2];
    const float* Wq1 = (const float*)d_in[3];
    const float* bq1 = (const float*)d_in[4];
    const float* Wq2 = (const float*)d_in[5];
    const float* bq2 = (const float*)d_in[6];
    const float* Wk1 = (const float*)d_in[7];
    const float* bk1 = (const float*)d_in[8];
    const float* Wk2 = (const float*)d_in[9];
    const float* bk2 = (const float*)d_in[10];
    const float* Wlq = (const float*)d_in[11];
    const float* blq = (const float*)d_in[12];
    const float* Wlk = (const float*)d_in[13];
    const float* blk = (const float*)d_in[14];
    float* out = (float*)d_out;

    const int SM3 = (2 * NTT * TS + NTT * EVD + 8 * 96) * 4;
    static int attr_done = 0;
    if (!attr_done) {
        cudaFuncSetAttribute(k_augment, cudaFuncAttributeMaxDynamicSharedMemorySize, AUG_SMEM);
        cudaFuncSetAttribute(k_proj, cudaFuncAttributeMaxDynamicSharedMemorySize, SM_TOT);
        cudaFuncSetAttribute(k_attn, cudaFuncAttributeMaxDynamicSharedMemorySize, SM3);
        attr_done = 1;
    }

    k_augment<<<dim3(8, 16), 256, AUG_SMEM>>>(q, k, Wq1, bq1, Wq2, bq2, Wk1, bk1, Wk2, bk2);
    k_proj<<<dim3(256, 2), 256, SM_TOT>>>(Wlq, blq, Wlk, blk);
    k_attn<<<dim3(4, 4), 256, SM3>>>(v, out);
}